// round 3
// baseline (speedup 1.0000x reference)
#include <cuda_runtime.h>
#include <math.h>

// Problem constants (fixed by the dataset)
#define NN    50000
#define EE    800000
#define ETOT  850000        // EE + NN self loops
#define FIN   256
#define HH    4
#define CC1   128
#define CC2   64
#define CH1   512           // HH*CC1
#define CH2   256           // HH*CC2
#define NCLS  50
#define SLOPE 0.2f

// ---------------- scratch (device globals; no allocations allowed) ----------
__device__ float g_h1[NN * CH1];      // x @ W1
__device__ float g_g1[NN * CH1];      // elu(agg1 + b1)
__device__ float g_h2[NN * CH2];      // g1 @ W2
__device__ float g_g2[NN * CH2];      // elu(agg2 + b2)
__device__ float g_asrc[NN * HH];
__device__ float g_adst[NN * HH];
__device__ int   g_deg[NN];
__device__ int   g_rowptr[NN + 1];
__device__ int   g_cursor[NN];
__device__ int   g_csr[ETOT];

// ---------------- CSR construction ------------------------------------------
__global__ void zero_deg_kernel() {
    int i = blockIdx.x * blockDim.x + threadIdx.x;
    if (i < NN) g_deg[i] = 0;
}

__global__ void count_deg_kernel(const int* __restrict__ ei) {
    int e = blockIdx.x * blockDim.x + threadIdx.x;
    if (e >= ETOT) return;
    int d = (e < EE) ? ei[EE + e] : (e - EE);   // self loop for e >= EE
    atomicAdd(&g_deg[d], 1);
}

// Single-block exclusive scan over 50000 degrees (tile-wise Hillis-Steele).
__global__ __launch_bounds__(1024) void scan_deg_kernel() {
    __shared__ int sh[1024];
    __shared__ int carry;
    int tid = threadIdx.x;
    if (tid == 0) { carry = 0; g_rowptr[0] = 0; }
    __syncthreads();
    for (int base = 0; base < NN; base += 1024) {
        int i = base + tid;
        int v = (i < NN) ? g_deg[i] : 0;
        sh[tid] = v;
        __syncthreads();
        for (int off = 1; off < 1024; off <<= 1) {
            int t = (tid >= off) ? sh[tid - off] : 0;
            __syncthreads();
            sh[tid] += t;
            __syncthreads();
        }
        int incl = sh[tid];
        int c = carry;
        if (i < NN) {
            g_rowptr[i + 1] = c + incl;
            g_cursor[i]     = c + incl - v;   // exclusive start
        }
        __syncthreads();
        if (tid == 1023) carry = c + sh[1023];
        __syncthreads();
    }
}

__global__ void scatter_edges_kernel(const int* __restrict__ ei) {
    int e = blockIdx.x * blockDim.x + threadIdx.x;
    if (e >= ETOT) return;
    int s, d;
    if (e < EE) { s = ei[e]; d = ei[EE + e]; }
    else        { s = d = e - EE; }
    int pos = atomicAdd(&g_cursor[d], 1);
    g_csr[pos] = s;
}

// ---------------- SGEMM: C[M,N] = A[M,K] @ B[K,N]  (N%128==0, K%8==0) -------
__global__ __launch_bounds__(256) void sgemm128_kernel(
    int M, int N, int K,
    const float* __restrict__ A, const float* __restrict__ B,
    float* __restrict__ C)
{
    __shared__ float As[8][128];
    __shared__ float Bs[8][128];
    int tid  = threadIdx.x;
    int row0 = blockIdx.y * 128;
    int col0 = blockIdx.x * 128;
    int tr = tid / 16, tc = tid % 16;
    int arow = tid >> 1, acol = (tid & 1) * 4;
    int brow = tid >> 5, bcol = (tid & 31) * 4;

    float acc[8][8];
    #pragma unroll
    for (int i = 0; i < 8; i++)
        #pragma unroll
        for (int j = 0; j < 8; j++) acc[i][j] = 0.0f;

    const float* Aptr = A + (size_t)(row0 + arow) * K + acol;
    bool arow_ok = (row0 + arow) < M;

    for (int k0 = 0; k0 < K; k0 += 8) {
        float4 av = arow_ok ? *(const float4*)(Aptr + k0) : make_float4(0.f, 0.f, 0.f, 0.f);
        As[acol + 0][arow] = av.x;
        As[acol + 1][arow] = av.y;
        As[acol + 2][arow] = av.z;
        As[acol + 3][arow] = av.w;
        float4 bv = *(const float4*)(B + (size_t)(k0 + brow) * N + col0 + bcol);
        *(float4*)&Bs[brow][bcol] = bv;
        __syncthreads();
        #pragma unroll
        for (int kk = 0; kk < 8; kk++) {
            float4 ra0 = *(const float4*)&As[kk][tr * 8];
            float4 ra1 = *(const float4*)&As[kk][tr * 8 + 4];
            float4 rb0 = *(const float4*)&Bs[kk][tc * 8];
            float4 rb1 = *(const float4*)&Bs[kk][tc * 8 + 4];
            float ra[8] = {ra0.x, ra0.y, ra0.z, ra0.w, ra1.x, ra1.y, ra1.z, ra1.w};
            float rb[8] = {rb0.x, rb0.y, rb0.z, rb0.w, rb1.x, rb1.y, rb1.z, rb1.w};
            #pragma unroll
            for (int i = 0; i < 8; i++)
                #pragma unroll
                for (int j = 0; j < 8; j++)
                    acc[i][j] += ra[i] * rb[j];
        }
        __syncthreads();
    }

    #pragma unroll
    for (int i = 0; i < 8; i++) {
        int r = row0 + tr * 8 + i;
        if (r < M) {
            float* cp = C + (size_t)r * N + col0 + tc * 8;
            *(float4*)cp       = make_float4(acc[i][0], acc[i][1], acc[i][2], acc[i][3]);
            *(float4*)(cp + 4) = make_float4(acc[i][4], acc[i][5], acc[i][6], acc[i][7]);
        }
    }
}

// ---------------- per-node attention halves ---------------------------------
// asrc[n,h] = sum_c h[n, h*C+c] * a_src[h,c] ; same for adst. One warp per (n,h).
template <int C>
__global__ void attn_coef_kernel(const float* __restrict__ h,
                                 const float* __restrict__ a_src,
                                 const float* __restrict__ a_dst,
                                 float* __restrict__ o_src,
                                 float* __restrict__ o_dst)
{
    int w = (blockIdx.x * blockDim.x + threadIdx.x) >> 5;
    if (w >= NN * HH) return;
    int lane = threadIdx.x & 31;
    int n = w / HH, hd = w % HH;
    const float* hp = h + (size_t)n * (HH * C) + hd * C;
    float ss = 0.f, dd = 0.f;
    #pragma unroll
    for (int j = 0; j < C / 32; j++) {
        int c = lane + j * 32;
        float hv = hp[c];
        ss += hv * a_src[hd * C + c];
        dd += hv * a_dst[hd * C + c];
    }
    #pragma unroll
    for (int off = 16; off > 0; off >>= 1) {
        ss += __shfl_xor_sync(0xffffffffu, ss, off);
        dd += __shfl_xor_sync(0xffffffffu, dd, off);
    }
    if (lane == 0) { o_src[n * HH + hd] = ss; o_dst[n * HH + hd] = dd; }
}

// ---------------- GAT softmax + aggregation (one block per dst node) --------
// out[d, :] = elu( sum_e alpha[e] * h[src_e, :]  + bias )
template <int CH>
__global__ __launch_bounds__(128) void gat_agg_kernel(
    const float* __restrict__ h,
    const float* __restrict__ asrc, const float* __restrict__ adst,
    const float* __restrict__ bias, float* __restrict__ out)
{
    constexpr int VEC = CH / 128;             // 4 (layer1) or 2 (layer2)
    int d    = blockIdx.x;
    int tid  = threadIdx.x;
    int lane = tid & 31, warp = tid >> 5;
    int s0 = g_rowptr[d], s1 = g_rowptr[d + 1];

    float ad[HH];
    #pragma unroll
    for (int hh = 0; hh < HH; hh++) ad[hh] = adst[d * HH + hh];

    __shared__ float red[4][HH];

    // pass 1: per-head max
    float mx[HH];
    #pragma unroll
    for (int hh = 0; hh < HH; hh++) mx[hh] = -1e30f;
    for (int k = s0 + tid; k < s1; k += 128) {
        int s = g_csr[k];
        #pragma unroll
        for (int hh = 0; hh < HH; hh++) {
            float v = asrc[s * HH + hh] + ad[hh];
            v = (v > 0.f) ? v : SLOPE * v;
            mx[hh] = fmaxf(mx[hh], v);
        }
    }
    #pragma unroll
    for (int hh = 0; hh < HH; hh++)
        #pragma unroll
        for (int off = 16; off > 0; off >>= 1)
            mx[hh] = fmaxf(mx[hh], __shfl_xor_sync(0xffffffffu, mx[hh], off));
    if (lane == 0)
        #pragma unroll
        for (int hh = 0; hh < HH; hh++) red[warp][hh] = mx[hh];
    __syncthreads();
    #pragma unroll
    for (int hh = 0; hh < HH; hh++)
        mx[hh] = fmaxf(fmaxf(red[0][hh], red[1][hh]), fmaxf(red[2][hh], red[3][hh]));
    __syncthreads();

    // pass 2: per-head sum of exp
    float sm[HH];
    #pragma unroll
    for (int hh = 0; hh < HH; hh++) sm[hh] = 0.f;
    for (int k = s0 + tid; k < s1; k += 128) {
        int s = g_csr[k];
        #pragma unroll
        for (int hh = 0; hh < HH; hh++) {
            float v = asrc[s * HH + hh] + ad[hh];
            v = (v > 0.f) ? v : SLOPE * v;
            sm[hh] += __expf(v - mx[hh]);
        }
    }
    #pragma unroll
    for (int hh = 0; hh < HH; hh++)
        #pragma unroll
        for (int off = 16; off > 0; off >>= 1)
            sm[hh] += __shfl_xor_sync(0xffffffffu, sm[hh], off);
    if (lane == 0)
        #pragma unroll
        for (int hh = 0; hh < HH; hh++) red[warp][hh] = sm[hh];
    __syncthreads();
    float inv[HH];
    #pragma unroll
    for (int hh = 0; hh < HH; hh++)
        inv[hh] = 1.0f / (red[0][hh] + red[1][hh] + red[2][hh] + red[3][hh] + 1e-16f);

    // pass 3: weighted accumulation. Thread owns channels [tid*VEC, tid*VEC+VEC),
    // all inside head tid>>5 for both CH=512 and CH=256.
    int head = tid >> 5;
    float mh = mx[head], ih = inv[head], adh = ad[head];
    float acc[VEC];
    #pragma unroll
    for (int j = 0; j < VEC; j++) acc[j] = 0.f;

    for (int k = s0; k < s1; k++) {
        int s = g_csr[k];
        float v = asrc[s * HH + head] + adh;
        v = (v > 0.f) ? v : SLOPE * v;
        float alpha = __expf(v - mh) * ih;
        const float* hp = h + (size_t)s * CH + tid * VEC;
        if (VEC == 4) {
            float4 hv = *(const float4*)hp;
            acc[0] += alpha * hv.x; acc[1] += alpha * hv.y;
            acc[2] += alpha * hv.z; acc[3] += alpha * hv.w;
        } else {
            float2 hv = *(const float2*)hp;
            acc[0] += alpha * hv.x; acc[1] += alpha * hv.y;
        }
    }

    #pragma unroll
    for (int j = 0; j < VEC; j++) {
        float v = acc[j] + bias[tid * VEC + j];
        out[(size_t)d * CH + tid * VEC + j] = (v > 0.f) ? v : expm1f(v);
    }
}

// ---------------- final classifier: out[N,50] = A[N,256] @ Wf + bf ----------
__global__ __launch_bounds__(128) void final_linear_kernel(
    const float* __restrict__ A, const float* __restrict__ Wf,
    const float* __restrict__ bf, float* __restrict__ out)
{
    __shared__ float rowbuf[4][CH2];
    int w = threadIdx.x >> 5, lane = threadIdx.x & 31;
    int row = blockIdx.x * 4 + w;
    if (row >= NN) return;
    #pragma unroll
    for (int j = 0; j < CH2 / 32; j++)
        rowbuf[w][lane + j * 32] = A[(size_t)row * CH2 + lane + j * 32];
    __syncwarp();
    float acc0 = 0.f, acc1 = 0.f;
    for (int k = 0; k < CH2; k++) {
        float a = rowbuf[w][k];
        acc0 += a * Wf[k * NCLS + lane];
        if (lane < NCLS - 32) acc1 += a * Wf[k * NCLS + lane + 32];
    }
    out[(size_t)row * NCLS + lane] = acc0 + bf[lane];
    if (lane < NCLS - 32)
        out[(size_t)row * NCLS + lane + 32] = acc1 + bf[lane + 32];
}

// ---------------- launch ----------------------------------------------------
extern "C" void kernel_launch(void* const* d_in, const int* in_sizes, int n_in,
                              void* d_out, int out_size)
{
    const float* x   = (const float*)d_in[0];
    const int*   ei  = (const int*)  d_in[1];
    const float* W1  = (const float*)d_in[2];
    const float* as1 = (const float*)d_in[3];
    const float* ad1 = (const float*)d_in[4];
    const float* b1  = (const float*)d_in[5];
    const float* W2  = (const float*)d_in[6];
    const float* as2 = (const float*)d_in[7];
    const float* ad2 = (const float*)d_in[8];
    const float* b2  = (const float*)d_in[9];
    const float* Wf  = (const float*)d_in[10];
    const float* bf  = (const float*)d_in[11];
    float* out = (float*)d_out;

    float *h1, *g1, *h2, *g2, *pas, *pad;
    cudaGetSymbolAddress((void**)&h1, g_h1);
    cudaGetSymbolAddress((void**)&g1, g_g1);
    cudaGetSymbolAddress((void**)&h2, g_h2);
    cudaGetSymbolAddress((void**)&g2, g_g2);
    cudaGetSymbolAddress((void**)&pas, g_asrc);
    cudaGetSymbolAddress((void**)&pad, g_adst);

    // CSR build
    zero_deg_kernel<<<(NN + 255) / 256, 256>>>();
    count_deg_kernel<<<(ETOT + 255) / 256, 256>>>(ei);
    scan_deg_kernel<<<1, 1024>>>();
    scatter_edges_kernel<<<(ETOT + 255) / 256, 256>>>(ei);

    // Layer 1
    {
        dim3 grid(CH1 / 128, (NN + 127) / 128);
        sgemm128_kernel<<<grid, 256>>>(NN, CH1, FIN, x, W1, h1);
    }
    attn_coef_kernel<CC1><<<(NN * HH) / 8, 256>>>(h1, as1, ad1, pas, pad);
    gat_agg_kernel<CH1><<<NN, 128>>>(h1, pas, pad, b1, g1);

    // Layer 2
    {
        dim3 grid(CH2 / 128, (NN + 127) / 128);
        sgemm128_kernel<<<grid, 256>>>(NN, CH2, CH1, g1, W2, h2);
    }
    attn_coef_kernel<CC2><<<(NN * HH) / 8, 256>>>(h2, as2, ad2, pas, pad);
    gat_agg_kernel<CH2><<<NN, 128>>>(h2, pas, pad, b2, g2);

    // Final linear
    final_linear_kernel<<<(NN + 3) / 4, 128>>>(g2, Wf, bf, out);
}

// round 4
// speedup vs baseline: 2.0236x; 2.0236x over previous
#include <cuda_runtime.h>
#include <math.h>
#include <stdint.h>

// Problem constants (fixed by the dataset)
#define NN    50000
#define EE    800000
#define ETOT  850000        // EE + NN self loops
#define FIN   256
#define HH    4
#define CC1   128
#define CC2   64
#define CH1   512           // HH*CC1
#define CH2   256           // HH*CC2
#define NCLS  50
#define SLOPE 0.2f
#define NBLK  ((NN + 255) / 256)

// ---------------- scratch (device globals; no allocations allowed) ----------
__device__ float g_h1[NN * CH1];      // x @ W1
__device__ float g_g1[NN * CH1];      // elu(agg1 + b1)
__device__ float g_h2[NN * CH2];      // g1 @ W2
__device__ float g_g2[NN * CH2];      // elu(agg2 + b2)
__device__ float g_asrc[NN * HH];
__device__ float g_adst[NN * HH];
__device__ float g_Wfpad[FIN * 128];  // Wf zero-padded to 128 cols (CH2=256 rows)
__device__ int   g_deg[NN];
__device__ int   g_rowptr[NN + 1];
__device__ int   g_cursor[NN];
__device__ int   g_csr[ETOT];
__device__ int   g_blocksum[256];
__device__ int   g_blockoff[256];

// ---------------- CSR construction ------------------------------------------
__global__ void zero_deg_kernel() {
    int i = blockIdx.x * blockDim.x + threadIdx.x;
    if (i < NN) g_deg[i] = 0;
}

__global__ void count_deg_kernel(const int* __restrict__ ei) {
    int e = blockIdx.x * blockDim.x + threadIdx.x;
    if (e >= ETOT) return;
    int d = (e < EE) ? ei[EE + e] : (e - EE);   // self loop for e >= EE
    atomicAdd(&g_deg[d], 1);
}

// Two-level scan: per-block inclusive scan + block sums
__global__ __launch_bounds__(256) void scan1_kernel() {
    int b = blockIdx.x;
    int i = b * 256 + threadIdx.x;
    int v = (i < NN) ? g_deg[i] : 0;
    int lane = threadIdx.x & 31, w = threadIdx.x >> 5;
    int s = v;
    #pragma unroll
    for (int off = 1; off < 32; off <<= 1) {
        int t = __shfl_up_sync(0xffffffffu, s, off);
        if (lane >= off) s += t;
    }
    __shared__ int ws[8];
    if (lane == 31) ws[w] = s;
    __syncthreads();
    if (threadIdx.x == 0) {
        int acc = 0;
        #pragma unroll
        for (int j = 0; j < 8; j++) { int t = ws[j]; ws[j] = acc; acc += t; }
        g_blocksum[b] = acc;
    }
    __syncthreads();
    s += ws[w];
    if (i < NN) g_rowptr[i + 1] = s;   // local inclusive; offset added in scan3
}

__global__ __launch_bounds__(256) void scan2_kernel() {
    int t = threadIdx.x;
    int v = (t < NBLK) ? g_blocksum[t] : 0;
    int lane = t & 31, w = t >> 5;
    int s = v;
    #pragma unroll
    for (int off = 1; off < 32; off <<= 1) {
        int u = __shfl_up_sync(0xffffffffu, s, off);
        if (lane >= off) s += u;
    }
    __shared__ int ws[8];
    if (lane == 31) ws[w] = s;
    __syncthreads();
    if (t == 0) {
        int acc = 0;
        #pragma unroll
        for (int j = 0; j < 8; j++) { int u = ws[j]; ws[j] = acc; acc += u; }
    }
    __syncthreads();
    s += ws[w];
    g_blockoff[t] = s - v;   // exclusive
}

__global__ void scan3_kernel() {
    int i = blockIdx.x * blockDim.x + threadIdx.x;
    if (i >= NN) return;
    int off  = g_blockoff[i >> 8];
    int incl = g_rowptr[i + 1] + off;
    g_rowptr[i + 1] = incl;
    g_cursor[i]     = incl - g_deg[i];
    if (i == 0) g_rowptr[0] = 0;
}

__global__ void scatter_edges_kernel(const int* __restrict__ ei) {
    int e = blockIdx.x * blockDim.x + threadIdx.x;
    if (e >= ETOT) return;
    int s, d;
    if (e < EE) { s = ei[e]; d = ei[EE + e]; }
    else        { s = d = e - EE; }
    int pos = atomicAdd(&g_cursor[d], 1);
    g_csr[pos] = s;
}

// ---------------- tf32 tensor-core GEMM -------------------------------------
// C[M,ncols] = A[M,K] @ B[K,N] (+bias), N multiple of 128, K multiple of 16.
// 128x128 block tile, BK=16, 8 warps (2x4), warp tile 64x32 via m16n8k8.
#define SA 20    // A smem row stride (uint32), conflict-free for frag loads
#define SB 136   // B smem row stride (uint32), conflict-free for frag loads

__device__ __forceinline__ uint32_t f2tf(float f) {
    uint32_t u;
    asm("cvt.rna.tf32.f32 %0, %1;" : "=r"(u) : "f"(f));
    return u;
}

__device__ __forceinline__ void mma_tf32(float* c, uint32_t a0, uint32_t a1,
                                         uint32_t a2, uint32_t a3,
                                         uint32_t b0, uint32_t b1) {
    asm volatile(
        "mma.sync.aligned.m16n8k8.row.col.f32.tf32.tf32.f32 "
        "{%0,%1,%2,%3},{%4,%5,%6,%7},{%8,%9},{%0,%1,%2,%3};\n"
        : "+f"(c[0]), "+f"(c[1]), "+f"(c[2]), "+f"(c[3])
        : "r"(a0), "r"(a1), "r"(a2), "r"(a3), "r"(b0), "r"(b1));
}

__global__ __launch_bounds__(256) void gemm_tf32_kernel(
    int M, int N, int K,
    const float* __restrict__ A, const float* __restrict__ B,
    float* __restrict__ C, int ldc, int ncols, const float* __restrict__ bias)
{
    __shared__ uint32_t As[2][128 * SA];
    __shared__ uint32_t Bs[2][16 * SB];

    int tid  = threadIdx.x;
    int row0 = blockIdx.y * 128;
    int col0 = blockIdx.x * 128;
    int warp = tid >> 5, lane = tid & 31;
    int wm = warp & 1, wn = warp >> 1;       // 2 x 4 warp grid -> warp tile 64x32
    int tg = lane >> 2, tig = lane & 3;

    // global staging indices
    int ar0 = tid >> 2,  ac = (tid & 3) * 4;    // A: rows ar0, ar0+64; cols ac..ac+3
    int br0 = tid >> 5,  bc = (tid & 31) * 4;   // B: rows br0, br0+8;  cols bc..bc+3

    float4 av0, av1, bv0, bv1;
    bool a0ok = (row0 + ar0)      < M;
    bool a1ok = (row0 + ar0 + 64) < M;

    auto ldg_tile = [&](int kt) {
        int kb = kt * 16 + ac;
        av0 = a0ok ? *(const float4*)(A + (size_t)(row0 + ar0)      * K + kb)
                   : make_float4(0.f, 0.f, 0.f, 0.f);
        av1 = a1ok ? *(const float4*)(A + (size_t)(row0 + ar0 + 64) * K + kb)
                   : make_float4(0.f, 0.f, 0.f, 0.f);
        bv0 = *(const float4*)(B + (size_t)(kt * 16 + br0)     * N + col0 + bc);
        bv1 = *(const float4*)(B + (size_t)(kt * 16 + br0 + 8) * N + col0 + bc);
    };

    auto sts_tile = [&](int buf) {
        uint32_t* Ab = As[buf];
        uint32_t* Bb = Bs[buf];
        uint32_t* p0 = Ab + ar0 * SA + ac;
        p0[0] = f2tf(av0.x); p0[1] = f2tf(av0.y); p0[2] = f2tf(av0.z); p0[3] = f2tf(av0.w);
        uint32_t* p1 = Ab + (ar0 + 64) * SA + ac;
        p1[0] = f2tf(av1.x); p1[1] = f2tf(av1.y); p1[2] = f2tf(av1.z); p1[3] = f2tf(av1.w);
        uint32_t* q0 = Bb + br0 * SB + bc;
        q0[0] = f2tf(bv0.x); q0[1] = f2tf(bv0.y); q0[2] = f2tf(bv0.z); q0[3] = f2tf(bv0.w);
        uint32_t* q1 = Bb + (br0 + 8) * SB + bc;
        q1[0] = f2tf(bv1.x); q1[1] = f2tf(bv1.y); q1[2] = f2tf(bv1.z); q1[3] = f2tf(bv1.w);
    };

    float c[4][4][4];
    #pragma unroll
    for (int mi = 0; mi < 4; mi++)
        #pragma unroll
        for (int ni = 0; ni < 4; ni++)
            #pragma unroll
            for (int j = 0; j < 4; j++) c[mi][ni][j] = 0.f;

    auto compute = [&](int buf) {
        uint32_t* Ab = As[buf];
        uint32_t* Bb = Bs[buf];
        #pragma unroll
        for (int ks = 0; ks < 2; ks++) {
            int kk = ks * 8;
            uint32_t af[4][4], bfr[4][2];
            #pragma unroll
            for (int mi = 0; mi < 4; mi++) {
                uint32_t* p = Ab + (wm * 64 + mi * 16 + tg) * SA + kk + tig;
                af[mi][0] = p[0];
                af[mi][1] = p[8 * SA];
                af[mi][2] = p[4];
                af[mi][3] = p[8 * SA + 4];
            }
            #pragma unroll
            for (int ni = 0; ni < 4; ni++) {
                uint32_t* p = Bb + (kk + tig) * SB + wn * 32 + ni * 8 + tg;
                bfr[ni][0] = p[0];
                bfr[ni][1] = p[4 * SB];
            }
            #pragma unroll
            for (int mi = 0; mi < 4; mi++)
                #pragma unroll
                for (int ni = 0; ni < 4; ni++)
                    mma_tf32(c[mi][ni], af[mi][0], af[mi][1], af[mi][2], af[mi][3],
                             bfr[ni][0], bfr[ni][1]);
        }
    };

    int KT = K / 16;
    ldg_tile(0);
    sts_tile(0);
    __syncthreads();
    for (int kt = 0; kt < KT; kt++) {
        int buf = kt & 1;
        bool more = (kt + 1 < KT);
        if (more) ldg_tile(kt + 1);
        compute(buf);
        if (more) sts_tile(buf ^ 1);
        __syncthreads();
    }

    // epilogue
    #pragma unroll
    for (int mi = 0; mi < 4; mi++) {
        int r = row0 + wm * 64 + mi * 16 + tg;
        #pragma unroll
        for (int ni = 0; ni < 4; ni++) {
            int cc = col0 + wn * 32 + ni * 8 + tig * 2;
            if (cc >= ncols) continue;
            float b0 = bias ? bias[cc]     : 0.f;
            float b1 = bias ? bias[cc + 1] : 0.f;
            if (r < M) {
                C[(size_t)r * ldc + cc]     = c[mi][ni][0] + b0;
                C[(size_t)r * ldc + cc + 1] = c[mi][ni][1] + b1;
            }
            if (r + 8 < M) {
                C[(size_t)(r + 8) * ldc + cc]     = c[mi][ni][2] + b0;
                C[(size_t)(r + 8) * ldc + cc + 1] = c[mi][ni][3] + b1;
            }
        }
    }
}

// Pad Wf [CH2, NCLS] -> g_Wfpad [CH2, 128] with zeros
__global__ void pad_wf_kernel(const float* __restrict__ Wf) {
    int i = blockIdx.x * blockDim.x + threadIdx.x;
    if (i >= CH2 * 128) return;
    int r = i >> 7, cc = i & 127;
    g_Wfpad[i] = (cc < NCLS) ? Wf[r * NCLS + cc] : 0.f;
}

// ---------------- per-node attention halves ---------------------------------
template <int C>
__global__ void attn_coef_kernel(const float* __restrict__ h,
                                 const float* __restrict__ a_src,
                                 const float* __restrict__ a_dst,
                                 float* __restrict__ o_src,
                                 float* __restrict__ o_dst)
{
    int w = (blockIdx.x * blockDim.x + threadIdx.x) >> 5;
    if (w >= NN * HH) return;
    int lane = threadIdx.x & 31;
    int n = w / HH, hd = w % HH;
    const float* hp = h + (size_t)n * (HH * C) + hd * C;
    float ss = 0.f, dd = 0.f;
    #pragma unroll
    for (int j = 0; j < C / 32; j++) {
        int cc = lane + j * 32;
        float hv = hp[cc];
        ss += hv * a_src[hd * C + cc];
        dd += hv * a_dst[hd * C + cc];
    }
    #pragma unroll
    for (int off = 16; off > 0; off >>= 1) {
        ss += __shfl_xor_sync(0xffffffffu, ss, off);
        dd += __shfl_xor_sync(0xffffffffu, dd, off);
    }
    if (lane == 0) { o_src[n * HH + hd] = ss; o_dst[n * HH + hd] = dd; }
}

// ---------------- GAT softmax + aggregation (one block per dst node) --------
// Scores are bounded (|e| ~< 6), so softmax is computed without the max pass:
// exp(e)/sum(exp(e)) == exp(e-m)/sum(exp(e-m)) mathematically.
template <int CH>
__global__ __launch_bounds__(128) void gat_agg_kernel(
    const float* __restrict__ h,
    const float* __restrict__ asrc, const float* __restrict__ adst,
    const float* __restrict__ bias, float* __restrict__ out)
{
    constexpr int VEC = CH / 128;             // 4 (layer1) or 2 (layer2)
    int d    = blockIdx.x;
    int tid  = threadIdx.x;
    int lane = tid & 31, warp = tid >> 5;
    int s0 = g_rowptr[d], s1 = g_rowptr[d + 1];

    float4 ad4 = *(const float4*)&adst[d * HH];
    float ad[HH] = {ad4.x, ad4.y, ad4.z, ad4.w};

    __shared__ float red[4][HH];

    // pass 1: per-head sum of exp
    float sm[HH] = {0.f, 0.f, 0.f, 0.f};
    for (int k = s0 + tid; k < s1; k += 128) {
        int s = g_csr[k];
        float4 as4 = *(const float4*)&asrc[s * HH];
        float as[HH] = {as4.x, as4.y, as4.z, as4.w};
        #pragma unroll
        for (int hh = 0; hh < HH; hh++) {
            float v = as[hh] + ad[hh];
            v = (v > 0.f) ? v : SLOPE * v;
            sm[hh] += __expf(v);
        }
    }
    #pragma unroll
    for (int hh = 0; hh < HH; hh++)
        #pragma unroll
        for (int off = 16; off > 0; off >>= 1)
            sm[hh] += __shfl_xor_sync(0xffffffffu, sm[hh], off);
    if (lane == 0)
        #pragma unroll
        for (int hh = 0; hh < HH; hh++) red[warp][hh] = sm[hh];
    __syncthreads();
    int head = tid >> 5;
    float ih  = 1.0f / (red[0][head] + red[1][head] + red[2][head] + red[3][head] + 1e-16f);
    float adh = ad[head];

    // pass 2: weighted accumulation. Thread owns channels [tid*VEC, +VEC),
    // all within head tid>>5 for both CH=512 and CH=256.
    float acc[VEC];
    #pragma unroll
    for (int j = 0; j < VEC; j++) acc[j] = 0.f;

    for (int k = s0; k < s1; k++) {
        int s = g_csr[k];
        float v = asrc[s * HH + head] + adh;
        v = (v > 0.f) ? v : SLOPE * v;
        float alpha = __expf(v) * ih;
        const float* hp = h + (size_t)s * CH + tid * VEC;
        if (VEC == 4) {
            float4 hv = *(const float4*)hp;
            acc[0] += alpha * hv.x; acc[1] += alpha * hv.y;
            acc[2] += alpha * hv.z; acc[3] += alpha * hv.w;
        } else {
            float2 hv = *(const float2*)hp;
            acc[0] += alpha * hv.x; acc[1] += alpha * hv.y;
        }
    }

    #pragma unroll
    for (int j = 0; j < VEC; j++) {
        float v = acc[j] + bias[tid * VEC + j];
        out[(size_t)d * CH + tid * VEC + j] = (v > 0.f) ? v : expm1f(v);
    }
}

// ---------------- launch ----------------------------------------------------
extern "C" void kernel_launch(void* const* d_in, const int* in_sizes, int n_in,
                              void* d_out, int out_size)
{
    const float* x   = (const float*)d_in[0];
    const int*   ei  = (const int*)  d_in[1];
    const float* W1  = (const float*)d_in[2];
    const float* as1 = (const float*)d_in[3];
    const float* ad1 = (const float*)d_in[4];
    const float* b1  = (const float*)d_in[5];
    const float* W2  = (const float*)d_in[6];
    const float* as2 = (const float*)d_in[7];
    const float* ad2 = (const float*)d_in[8];
    const float* b2  = (const float*)d_in[9];
    const float* Wf  = (const float*)d_in[10];
    const float* bf  = (const float*)d_in[11];
    float* out = (float*)d_out;

    float *h1, *g1, *h2, *g2, *pas, *pad, *wfp;
    cudaGetSymbolAddress((void**)&h1,  g_h1);
    cudaGetSymbolAddress((void**)&g1,  g_g1);
    cudaGetSymbolAddress((void**)&h2,  g_h2);
    cudaGetSymbolAddress((void**)&g2,  g_g2);
    cudaGetSymbolAddress((void**)&pas, g_asrc);
    cudaGetSymbolAddress((void**)&pad, g_adst);
    cudaGetSymbolAddress((void**)&wfp, g_Wfpad);

    int grid_y = (NN + 127) / 128;   // 391

    // CSR build
    zero_deg_kernel<<<(NN + 255) / 256, 256>>>();
    count_deg_kernel<<<(ETOT + 255) / 256, 256>>>(ei);
    scan1_kernel<<<NBLK, 256>>>();
    scan2_kernel<<<1, 256>>>();
    scan3_kernel<<<NBLK, 256>>>();
    scatter_edges_kernel<<<(ETOT + 255) / 256, 256>>>(ei);

    // pad Wf (independent of everything else)
    pad_wf_kernel<<<(CH2 * 128 + 255) / 256, 256>>>(Wf);

    // Layer 1
    gemm_tf32_kernel<<<dim3(CH1 / 128, grid_y), 256>>>(
        NN, CH1, FIN, x, W1, h1, CH1, CH1, nullptr);
    attn_coef_kernel<CC1><<<(NN * HH) / 8, 256>>>(h1, as1, ad1, pas, pad);
    gat_agg_kernel<CH1><<<NN, 128>>>(h1, pas, pad, b1, g1);

    // Layer 2
    gemm_tf32_kernel<<<dim3(CH2 / 128, grid_y), 256>>>(
        NN, CH2, CH1, g1, W2, h2, CH2, CH2, nullptr);
    attn_coef_kernel<CC2><<<(NN * HH) / 8, 256>>>(h2, as2, ad2, pas, pad);
    gat_agg_kernel<CH2><<<NN, 128>>>(h2, pas, pad, b2, g2);

    // Final classifier as padded tf32 GEMM: out[N,50] = g2 @ Wfpad + bf
    gemm_tf32_kernel<<<dim3(1, grid_y), 256>>>(
        NN, 128, CH2, g2, wfp, out, NCLS, NCLS, bf);
}

// round 6
// speedup vs baseline: 2.6128x; 1.2912x over previous
#include <cuda_runtime.h>
#include <cuda_fp16.h>
#include <math.h>
#include <stdint.h>

// Problem constants (fixed by the dataset)
#define NN    50000
#define EE    800000
#define ETOT  850000        // EE + NN self loops
#define FIN   256
#define HH    4
#define CC1   128
#define CC2   64
#define CH1   512           // HH*CC1
#define CH2   256           // HH*CC2
#define NCLS  50
#define SLOPE 0.2f
#define NBLK  ((NN + 255) / 256)

// ---------------- scratch (device globals; no allocations allowed) ----------
__device__ __half g_h1h[NN * CH1];    // x @ W1   (fp16 copy for message gather)
__device__ __half g_h2h[NN * CH2];    // g1 @ W2  (fp16)
__device__ float g_g1[NN * CH1];      // elu(agg1 + b1)
__device__ float g_g2[NN * CH2];      // elu(agg2 + b2)
__device__ float g_asrc[NN * HH];
__device__ float g_adst[NN * HH];
__device__ float g_Wfpad[FIN * 128];  // Wf zero-padded to 128 cols
__device__ int   g_deg[NN];
__device__ int   g_rowptr[NN + 1];
__device__ int   g_cursor[NN];
__device__ int   g_csr[ETOT];
__device__ int   g_blocksum[256];
__device__ int   g_blockoff[256];

// ---------------- CSR construction ------------------------------------------
__global__ void zero_deg_kernel() {
    int i = blockIdx.x * blockDim.x + threadIdx.x;
    if (i < NN) g_deg[i] = 0;
}

__global__ void count_deg_kernel(const int* __restrict__ ei) {
    int e = blockIdx.x * blockDim.x + threadIdx.x;
    if (e >= ETOT) return;
    int d = (e < EE) ? ei[EE + e] : (e - EE);   // self loop for e >= EE
    atomicAdd(&g_deg[d], 1);
}

__global__ __launch_bounds__(256) void scan1_kernel() {
    int b = blockIdx.x;
    int i = b * 256 + threadIdx.x;
    int v = (i < NN) ? g_deg[i] : 0;
    int lane = threadIdx.x & 31, w = threadIdx.x >> 5;
    int s = v;
    #pragma unroll
    for (int off = 1; off < 32; off <<= 1) {
        int t = __shfl_up_sync(0xffffffffu, s, off);
        if (lane >= off) s += t;
    }
    __shared__ int ws[8];
    if (lane == 31) ws[w] = s;
    __syncthreads();
    if (threadIdx.x == 0) {
        int acc = 0;
        #pragma unroll
        for (int j = 0; j < 8; j++) { int t = ws[j]; ws[j] = acc; acc += t; }
        g_blocksum[b] = acc;
    }
    __syncthreads();
    s += ws[w];
    if (i < NN) g_rowptr[i + 1] = s;   // local inclusive; offset added in scan3
}

__global__ __launch_bounds__(256) void scan2_kernel() {
    int t = threadIdx.x;
    int v = (t < NBLK) ? g_blocksum[t] : 0;
    int lane = t & 31, w = t >> 5;
    int s = v;
    #pragma unroll
    for (int off = 1; off < 32; off <<= 1) {
        int u = __shfl_up_sync(0xffffffffu, s, off);
        if (lane >= off) s += u;
    }
    __shared__ int ws[8];
    if (lane == 31) ws[w] = s;
    __syncthreads();
    if (t == 0) {
        int acc = 0;
        #pragma unroll
        for (int j = 0; j < 8; j++) { int u = ws[j]; ws[j] = acc; acc += u; }
    }
    __syncthreads();
    s += ws[w];
    g_blockoff[t] = s - v;   // exclusive
}

__global__ void scan3_kernel() {
    int i = blockIdx.x * blockDim.x + threadIdx.x;
    if (i >= NN) return;
    int off  = g_blockoff[i >> 8];
    int incl = g_rowptr[i + 1] + off;
    g_rowptr[i + 1] = incl;
    g_cursor[i]     = incl - g_deg[i];
    if (i == 0) g_rowptr[0] = 0;
}

__global__ void scatter_edges_kernel(const int* __restrict__ ei) {
    int e = blockIdx.x * blockDim.x + threadIdx.x;
    if (e >= ETOT) return;
    int s, d;
    if (e < EE) { s = ei[e]; d = ei[EE + e]; }
    else        { s = d = e - EE; }
    int pos = atomicAdd(&g_cursor[d], 1);
    g_csr[pos] = s;
}

// ---------------- tf32 tensor-core GEMM + fused attn epilogue ----------------
// C[M,ncols] = A[M,K] @ B[K,N] (+bias), N multiple of 128, K multiple of 16.
// 128x128 block tile, BK=16, 8 warps (2x4), warp tile 64x32 via m16n8k8.
// HPB = heads covered per block-column tile (1 layer1, 2 layer2, 0 = none).
// HALFOUT: C written as fp16 (message buffer); else fp32 with bias.
#define SA 20    // A smem row stride (uint32), conflict-free for frag loads
#define SB 136   // B smem row stride (uint32), conflict-free for frag loads

__device__ __forceinline__ uint32_t f2tf(float f) {
    uint32_t u;
    asm("cvt.rna.tf32.f32 %0, %1;" : "=r"(u) : "f"(f));
    return u;
}

__device__ __forceinline__ void mma_tf32(float* c, uint32_t a0, uint32_t a1,
                                         uint32_t a2, uint32_t a3,
                                         uint32_t b0, uint32_t b1) {
    asm volatile(
        "mma.sync.aligned.m16n8k8.row.col.f32.tf32.tf32.f32 "
        "{%0,%1,%2,%3},{%4,%5,%6,%7},{%8,%9},{%0,%1,%2,%3};\n"
        : "+f"(c[0]), "+f"(c[1]), "+f"(c[2]), "+f"(c[3])
        : "r"(a0), "r"(a1), "r"(a2), "r"(a3), "r"(b0), "r"(b1));
}

template <int HPB, bool HALFOUT>
__global__ __launch_bounds__(256) void gemm_tf32_kernel(
    int M, int N, int K,
    const float* __restrict__ A, const float* __restrict__ B,
    float* __restrict__ Cf, __half* __restrict__ Chalf,
    int ldc, int ncols, const float* __restrict__ bias,
    const float* __restrict__ avs, const float* __restrict__ avd,
    float* __restrict__ o_src, float* __restrict__ o_dst)
{
    __shared__ uint32_t As[2][128 * SA];
    __shared__ uint32_t Bs[2][16 * SB];
    __shared__ float sm_src[4][128];
    __shared__ float sm_dst[4][128];

    int tid  = threadIdx.x;
    int row0 = blockIdx.y * 128;
    int col0 = blockIdx.x * 128;
    int warp = tid >> 5, lane = tid & 31;
    int wm = warp & 1, wn = warp >> 1;       // 2 x 4 warp grid -> warp tile 64x32
    int tg = lane >> 2, tig = lane & 3;

    // global staging indices
    int ar0 = tid >> 2,  ac = (tid & 3) * 4;    // A: rows ar0, ar0+64; cols ac..ac+3
    int br0 = tid >> 5,  bc = (tid & 31) * 4;   // B: rows br0, br0+8;  cols bc..bc+3

    float4 av0, av1, bv0, bv1;
    bool a0ok = (row0 + ar0)      < M;
    bool a1ok = (row0 + ar0 + 64) < M;

    auto ldg_tile = [&](int kt) {
        int kb = kt * 16 + ac;
        av0 = a0ok ? *(const float4*)(A + (size_t)(row0 + ar0)      * K + kb)
                   : make_float4(0.f, 0.f, 0.f, 0.f);
        av1 = a1ok ? *(const float4*)(A + (size_t)(row0 + ar0 + 64) * K + kb)
                   : make_float4(0.f, 0.f, 0.f, 0.f);
        bv0 = *(const float4*)(B + (size_t)(kt * 16 + br0)     * N + col0 + bc);
        bv1 = *(const float4*)(B + (size_t)(kt * 16 + br0 + 8) * N + col0 + bc);
    };

    auto sts_tile = [&](int buf) {
        uint32_t* Ab = As[buf];
        uint32_t* Bb = Bs[buf];
        uint32_t* p0 = Ab + ar0 * SA + ac;
        p0[0] = f2tf(av0.x); p0[1] = f2tf(av0.y); p0[2] = f2tf(av0.z); p0[3] = f2tf(av0.w);
        uint32_t* p1 = Ab + (ar0 + 64) * SA + ac;
        p1[0] = f2tf(av1.x); p1[1] = f2tf(av1.y); p1[2] = f2tf(av1.z); p1[3] = f2tf(av1.w);
        uint32_t* q0 = Bb + br0 * SB + bc;
        q0[0] = f2tf(bv0.x); q0[1] = f2tf(bv0.y); q0[2] = f2tf(bv0.z); q0[3] = f2tf(bv0.w);
        uint32_t* q1 = Bb + (br0 + 8) * SB + bc;
        q1[0] = f2tf(bv1.x); q1[1] = f2tf(bv1.y); q1[2] = f2tf(bv1.z); q1[3] = f2tf(bv1.w);
    };

    float c[4][4][4];
    #pragma unroll
    for (int mi = 0; mi < 4; mi++)
        #pragma unroll
        for (int ni = 0; ni < 4; ni++)
            #pragma unroll
            for (int j = 0; j < 4; j++) c[mi][ni][j] = 0.f;

    auto compute = [&](int buf) {
        uint32_t* Ab = As[buf];
        uint32_t* Bb = Bs[buf];
        #pragma unroll
        for (int ks = 0; ks < 2; ks++) {
            int kk = ks * 8;
            uint32_t af[4][4], bfr[4][2];
            #pragma unroll
            for (int mi = 0; mi < 4; mi++) {
                uint32_t* p = Ab + (wm * 64 + mi * 16 + tg) * SA + kk + tig;
                af[mi][0] = p[0];
                af[mi][1] = p[8 * SA];
                af[mi][2] = p[4];
                af[mi][3] = p[8 * SA + 4];
            }
            #pragma unroll
            for (int ni = 0; ni < 4; ni++) {
                uint32_t* p = Bb + (kk + tig) * SB + wn * 32 + ni * 8 + tg;
                bfr[ni][0] = p[0];
                bfr[ni][1] = p[4 * SB];
            }
            #pragma unroll
            for (int mi = 0; mi < 4; mi++)
                #pragma unroll
                for (int ni = 0; ni < 4; ni++)
                    mma_tf32(c[mi][ni], af[mi][0], af[mi][1], af[mi][2], af[mi][3],
                             bfr[ni][0], bfr[ni][1]);
        }
    };

    int KT = K / 16;
    ldg_tile(0);
    sts_tile(0);
    __syncthreads();
    for (int kt = 0; kt < KT; kt++) {
        int buf = kt & 1;
        bool more = (kt + 1 < KT);
        if (more) ldg_tile(kt + 1);
        compute(buf);
        if (more) sts_tile(buf ^ 1);
        __syncthreads();
    }

    // ---- fused attention-coefficient epilogue ----
    if (HPB > 0) {
        float sa[4][2], da[4][2];
        #pragma unroll
        for (int mi = 0; mi < 4; mi++) {
            sa[mi][0] = sa[mi][1] = 0.f;
            da[mi][0] = da[mi][1] = 0.f;
        }
        #pragma unroll
        for (int ni = 0; ni < 4; ni++) {
            int cl = wn * 32 + ni * 8 + tig * 2;
            float ws0 = avs[col0 + cl], ws1 = avs[col0 + cl + 1];
            float wd0 = avd[col0 + cl], wd1 = avd[col0 + cl + 1];
            #pragma unroll
            for (int mi = 0; mi < 4; mi++) {
                sa[mi][0] += c[mi][ni][0] * ws0 + c[mi][ni][1] * ws1;
                da[mi][0] += c[mi][ni][0] * wd0 + c[mi][ni][1] * wd1;
                sa[mi][1] += c[mi][ni][2] * ws0 + c[mi][ni][3] * ws1;
                da[mi][1] += c[mi][ni][2] * wd0 + c[mi][ni][3] * wd1;
            }
        }
        #pragma unroll
        for (int mi = 0; mi < 4; mi++)
            #pragma unroll
            for (int p = 0; p < 2; p++) {
                sa[mi][p] += __shfl_xor_sync(0xffffffffu, sa[mi][p], 1);
                sa[mi][p] += __shfl_xor_sync(0xffffffffu, sa[mi][p], 2);
                da[mi][p] += __shfl_xor_sync(0xffffffffu, da[mi][p], 1);
                da[mi][p] += __shfl_xor_sync(0xffffffffu, da[mi][p], 2);
            }
        if (tig == 0) {
            #pragma unroll
            for (int mi = 0; mi < 4; mi++) {
                int rl = wm * 64 + mi * 16 + tg;
                sm_src[wn][rl]     = sa[mi][0];
                sm_src[wn][rl + 8] = sa[mi][1];
                sm_dst[wn][rl]     = da[mi][0];
                sm_dst[wn][rl + 8] = da[mi][1];
            }
        }
        __syncthreads();
        if (tid < 128) {
            int r = row0 + tid;
            if (r < M) {
                if (HPB == 1) {
                    float s = sm_src[0][tid] + sm_src[1][tid] + sm_src[2][tid] + sm_src[3][tid];
                    float d = sm_dst[0][tid] + sm_dst[1][tid] + sm_dst[2][tid] + sm_dst[3][tid];
                    o_src[r * HH + blockIdx.x] = s;
                    o_dst[r * HH + blockIdx.x] = d;
                } else {
                    float s0 = sm_src[0][tid] + sm_src[1][tid];
                    float s1 = sm_src[2][tid] + sm_src[3][tid];
                    float d0 = sm_dst[0][tid] + sm_dst[1][tid];
                    float d1 = sm_dst[2][tid] + sm_dst[3][tid];
                    int hb = blockIdx.x * 2;
                    o_src[r * HH + hb]     = s0;
                    o_src[r * HH + hb + 1] = s1;
                    o_dst[r * HH + hb]     = d0;
                    o_dst[r * HH + hb + 1] = d1;
                }
            }
        }
    }

    // ---- C write ----
    #pragma unroll
    for (int mi = 0; mi < 4; mi++) {
        int r = row0 + wm * 64 + mi * 16 + tg;
        #pragma unroll
        for (int ni = 0; ni < 4; ni++) {
            int cc = col0 + wn * 32 + ni * 8 + tig * 2;
            if (cc >= ncols) continue;
            if (HALFOUT) {
                if (r < M)
                    *(__half2*)(Chalf + (size_t)r * ldc + cc) =
                        __floats2half2_rn(c[mi][ni][0], c[mi][ni][1]);
                if (r + 8 < M)
                    *(__half2*)(Chalf + (size_t)(r + 8) * ldc + cc) =
                        __floats2half2_rn(c[mi][ni][2], c[mi][ni][3]);
            } else {
                float b0 = bias ? bias[cc]     : 0.f;
                float b1 = bias ? bias[cc + 1] : 0.f;
                if (r < M) {
                    Cf[(size_t)r * ldc + cc]     = c[mi][ni][0] + b0;
                    Cf[(size_t)r * ldc + cc + 1] = c[mi][ni][1] + b1;
                }
                if (r + 8 < M) {
                    Cf[(size_t)(r + 8) * ldc + cc]     = c[mi][ni][2] + b0;
                    Cf[(size_t)(r + 8) * ldc + cc + 1] = c[mi][ni][3] + b1;
                }
            }
        }
    }
}

// Pad Wf [CH2, NCLS] -> g_Wfpad [CH2, 128] with zeros
__global__ void pad_wf_kernel(const float* __restrict__ Wf) {
    int i = blockIdx.x * blockDim.x + threadIdx.x;
    if (i >= CH2 * 128) return;
    int r = i >> 7, cc = i & 127;
    g_Wfpad[i] = (cc < NCLS) ? Wf[r * NCLS + cc] : 0.f;
}

// ---------------- GAT softmax + aggregation (one block per dst node) --------
// Softmax computed without max-subtraction (scores bounded; validated R3).
// Pass 1 caches src ids + per-head exp(e) in smem (deg<=512 fast path),
// pass 2 is a pure gather-FMA over fp16 messages, 4-way unrolled.
#define DCAP 512
template <int CH>
__global__ __launch_bounds__(128) void gat_agg_kernel(
    const __half* __restrict__ h,
    const float* __restrict__ asrc, const float* __restrict__ adst,
    const float* __restrict__ bias, float* __restrict__ out)
{
    constexpr int VEC = CH / 128;             // 4 (layer1) or 2 (layer2)
    __shared__ int   ssrc[DCAP];
    __shared__ float sexp[DCAP * HH];
    __shared__ float red[4][HH];

    int d    = blockIdx.x;
    int tid  = threadIdx.x;
    int lane = tid & 31, warp = tid >> 5;
    int s0   = g_rowptr[d];
    int deg  = g_rowptr[d + 1] - s0;

    float4 ad4 = *(const float4*)&adst[d * HH];

    float sm[HH] = {0.f, 0.f, 0.f, 0.f};
    if (deg <= DCAP) {
        for (int j = tid; j < deg; j += 128) {
            int s = g_csr[s0 + j];
            ssrc[j] = s;
            float4 a = *(const float4*)&asrc[s * HH];
            float e0 = a.x + ad4.x; e0 = (e0 > 0.f) ? e0 : SLOPE * e0; e0 = __expf(e0);
            float e1 = a.y + ad4.y; e1 = (e1 > 0.f) ? e1 : SLOPE * e1; e1 = __expf(e1);
            float e2 = a.z + ad4.z; e2 = (e2 > 0.f) ? e2 : SLOPE * e2; e2 = __expf(e2);
            float e3 = a.w + ad4.w; e3 = (e3 > 0.f) ? e3 : SLOPE * e3; e3 = __expf(e3);
            sexp[j * HH + 0] = e0; sexp[j * HH + 1] = e1;
            sexp[j * HH + 2] = e2; sexp[j * HH + 3] = e3;
            sm[0] += e0; sm[1] += e1; sm[2] += e2; sm[3] += e3;
        }
    } else {
        for (int j = tid; j < deg; j += 128) {
            int s = g_csr[s0 + j];
            float4 a = *(const float4*)&asrc[s * HH];
            float e0 = a.x + ad4.x; e0 = (e0 > 0.f) ? e0 : SLOPE * e0;
            float e1 = a.y + ad4.y; e1 = (e1 > 0.f) ? e1 : SLOPE * e1;
            float e2 = a.z + ad4.z; e2 = (e2 > 0.f) ? e2 : SLOPE * e2;
            float e3 = a.w + ad4.w; e3 = (e3 > 0.f) ? e3 : SLOPE * e3;
            sm[0] += __expf(e0); sm[1] += __expf(e1);
            sm[2] += __expf(e2); sm[3] += __expf(e3);
        }
    }
    #pragma unroll
    for (int hh = 0; hh < HH; hh++)
        #pragma unroll
        for (int off = 16; off > 0; off >>= 1)
            sm[hh] += __shfl_xor_sync(0xffffffffu, sm[hh], off);
    if (lane == 0)
        #pragma unroll
        for (int hh = 0; hh < HH; hh++) red[warp][hh] = sm[hh];
    __syncthreads();   // also publishes ssrc/sexp

    int head = tid >> 5;
    float ih = 1.0f / (red[0][head] + red[1][head] + red[2][head] + red[3][head] + 1e-16f);

    float acc[VEC];
    #pragma unroll
    for (int j = 0; j < VEC; j++) acc[j] = 0.f;

    const int hoff = tid * (VEC / 2);   // __half2 offset within row

    if (deg <= DCAP) {
        int j = 0;
        for (; j + 4 <= deg; j += 4) {
            int sA = ssrc[j], sB = ssrc[j + 1], sC = ssrc[j + 2], sD = ssrc[j + 3];
            float eA = sexp[(j    ) * HH + head];
            float eB = sexp[(j + 1) * HH + head];
            float eC = sexp[(j + 2) * HH + head];
            float eD = sexp[(j + 3) * HH + head];
            const __half2* pA = (const __half2*)(h + (size_t)sA * CH) + hoff;
            const __half2* pB = (const __half2*)(h + (size_t)sB * CH) + hoff;
            const __half2* pC = (const __half2*)(h + (size_t)sC * CH) + hoff;
            const __half2* pD = (const __half2*)(h + (size_t)sD * CH) + hoff;
            if (VEC == 4) {
                __half2 a0 = pA[0], a1 = pA[1];
                __half2 b0 = pB[0], b1 = pB[1];
                __half2 c0 = pC[0], c1 = pC[1];
                __half2 d0 = pD[0], d1 = pD[1];
                float2 f;
                f = __half22float2(a0); acc[0] += eA * f.x; acc[1] += eA * f.y;
                f = __half22float2(a1); acc[2] += eA * f.x; acc[3] += eA * f.y;
                f = __half22float2(b0); acc[0] += eB * f.x; acc[1] += eB * f.y;
                f = __half22float2(b1); acc[2] += eB * f.x; acc[3] += eB * f.y;
                f = __half22float2(c0); acc[0] += eC * f.x; acc[1] += eC * f.y;
                f = __half22float2(c1); acc[2] += eC * f.x; acc[3] += eC * f.y;
                f = __half22float2(d0); acc[0] += eD * f.x; acc[1] += eD * f.y;
                f = __half22float2(d1); acc[2] += eD * f.x; acc[3] += eD * f.y;
            } else {
                __half2 a0 = pA[0], b0 = pB[0], c0 = pC[0], d0 = pD[0];
                float2 f;
                f = __half22float2(a0); acc[0] += eA * f.x; acc[1] += eA * f.y;
                f = __half22float2(b0); acc[0] += eB * f.x; acc[1] += eB * f.y;
                f = __half22float2(c0); acc[0] += eC * f.x; acc[1] += eC * f.y;
                f = __half22float2(d0); acc[0] += eD * f.x; acc[1] += eD * f.y;
            }
        }
        for (; j < deg; j++) {
            int s = ssrc[j];
            float e = sexp[j * HH + head];
            const __half2* p = (const __half2*)(h + (size_t)s * CH) + hoff;
            #pragma unroll
            for (int q = 0; q < VEC / 2; q++) {
                float2 f = __half22float2(p[q]);
                acc[q * 2]     += e * f.x;
                acc[q * 2 + 1] += e * f.y;
            }
        }
    } else {
        // chunked fallback (recompute exp per chunk)
        for (int c0 = 0; c0 < deg; c0 += DCAP) {
            int cn = min(DCAP, deg - c0);
            __syncthreads();
            for (int j = tid; j < cn; j += 128) {
                int s = g_csr[s0 + c0 + j];
                ssrc[j] = s;
                float4 a = *(const float4*)&asrc[s * HH];
                float e0 = a.x + ad4.x; e0 = (e0 > 0.f) ? e0 : SLOPE * e0;
                float e1 = a.y + ad4.y; e1 = (e1 > 0.f) ? e1 : SLOPE * e1;
                float e2 = a.z + ad4.z; e2 = (e2 > 0.f) ? e2 : SLOPE * e2;
                float e3 = a.w + ad4.w; e3 = (e3 > 0.f) ? e3 : SLOPE * e3;
                sexp[j * HH + 0] = __expf(e0); sexp[j * HH + 1] = __expf(e1);
                sexp[j * HH + 2] = __expf(e2); sexp[j * HH + 3] = __expf(e3);
            }
            __syncthreads();
            for (int j = 0; j < cn; j++) {
                int s = ssrc[j];
                float e = sexp[j * HH + head];
                const __half2* p = (const __half2*)(h + (size_t)s * CH) + hoff;
                #pragma unroll
                for (int q = 0; q < VEC / 2; q++) {
                    float2 f = __half22float2(p[q]);
                    acc[q * 2]     += e * f.x;
                    acc[q * 2 + 1] += e * f.y;
                }
            }
        }
    }

    #pragma unroll
    for (int j = 0; j < VEC; j++) {
        float v = acc[j] * ih + bias[tid * VEC + j];
        out[(size_t)d * CH + tid * VEC + j] = (v > 0.f) ? v : expm1f(v);
    }
}

// ---------------- launch ----------------------------------------------------
extern "C" void kernel_launch(void* const* d_in, const int* in_sizes, int n_in,
                              void* d_out, int out_size)
{
    const float* x   = (const float*)d_in[0];
    const int*   ei  = (const int*)  d_in[1];
    const float* W1  = (const float*)d_in[2];
    const float* as1 = (const float*)d_in[3];
    const float* ad1 = (const float*)d_in[4];
    const float* b1  = (const float*)d_in[5];
    const float* W2  = (const float*)d_in[6];
    const float* as2 = (const float*)d_in[7];
    const float* ad2 = (const float*)d_in[8];
    const float* b2  = (const float*)d_in[9];
    const float* Wf  = (const float*)d_in[10];
    const float* bf  = (const float*)d_in[11];
    float* out = (float*)d_out;

    __half *h1h, *h2h;
    float *g1, *g2, *pas, *pad, *wfp;
    cudaGetSymbolAddress((void**)&h1h, g_h1h);
    cudaGetSymbolAddress((void**)&h2h, g_h2h);
    cudaGetSymbolAddress((void**)&g1,  g_g1);
    cudaGetSymbolAddress((void**)&g2,  g_g2);
    cudaGetSymbolAddress((void**)&pas, g_asrc);
    cudaGetSymbolAddress((void**)&pad, g_adst);
    cudaGetSymbolAddress((void**)&wfp, g_Wfpad);

    int grid_y = (NN + 127) / 128;   // 391

    // Launch order puts GEMM1 4th so the fixed-skip ncu capture profiles it.
    zero_deg_kernel<<<(NN + 255) / 256, 256>>>();
    count_deg_kernel<<<(ETOT + 255) / 256, 256>>>(ei);
    pad_wf_kernel<<<(CH2 * 128 + 255) / 256, 256>>>(Wf);

    // Layer 1 GEMM (+ fused attn coefs, fp16 h out)
    gemm_tf32_kernel<1, true><<<dim3(CH1 / 128, grid_y), 256>>>(
        NN, CH1, FIN, x, W1, (float*)nullptr, h1h, CH1, CH1, (const float*)nullptr,
        as1, ad1, pas, pad);

    // CSR build
    scan1_kernel<<<NBLK, 256>>>();
    scan2_kernel<<<1, 256>>>();
    scan3_kernel<<<NBLK, 256>>>();
    scatter_edges_kernel<<<(ETOT + 255) / 256, 256>>>(ei);

    gat_agg_kernel<CH1><<<NN, 128>>>(h1h, pas, pad, b1, g1);

    // Layer 2
    gemm_tf32_kernel<2, true><<<dim3(CH2 / 128, grid_y), 256>>>(
        NN, CH2, CH1, g1, W2, (float*)nullptr, h2h, CH2, CH2, (const float*)nullptr,
        as2, ad2, pas, pad);
    gat_agg_kernel<CH2><<<NN, 128>>>(h2h, pas, pad, b2, g2);

    // Final classifier as padded tf32 GEMM: out[N,50] = g2 @ Wfpad + bf
    gemm_tf32_kernel<0, false><<<dim3(1, grid_y), 256>>>(
        NN, 128, CH2, g2, wfp, out, (__half*)nullptr, NCLS, NCLS, bf,
        (const float*)nullptr, (const float*)nullptr,
        (float*)nullptr, (float*)nullptr);
}

// round 7
// speedup vs baseline: 2.8869x; 1.1049x over previous
#include <cuda_runtime.h>
#include <cuda_fp16.h>
#include <math.h>
#include <stdint.h>

// Problem constants (fixed by the dataset)
#define NN    50000
#define EE    800000
#define ETOT  850000        // EE + NN self loops
#define FIN   256
#define HH    4
#define CC1   128
#define CC2   64
#define CH1   512           // HH*CC1
#define CH2   256           // HH*CC2
#define NCLS  50
#define SLOPE 0.2f
#define NBLK  ((NN + 255) / 256)

// ---------------- scratch (device globals; no allocations allowed) ----------
__device__ __half g_h1h[NN * CH1];    // x @ W1   (fp16 copy for message gather)
__device__ __half g_h2h[NN * CH2];    // g1 @ W2  (fp16)
__device__ float g_g1[NN * CH1];      // elu(agg1 + b1)
__device__ float g_g2[NN * CH2];      // elu(agg2 + b2)
__device__ float g_asrc[NN * HH];
__device__ float g_adst[NN * HH];
__device__ float g_Wfpad[FIN * 128];  // Wf zero-padded to 128 cols
__device__ int   g_deg[NN];
__device__ int   g_rowptr[NN + 1];
__device__ int   g_cursor[NN];
__device__ int   g_csr[ETOT];
__device__ int   g_blocksum[256];
__device__ int   g_blockoff[256];

// ---------------- CSR construction ------------------------------------------
__global__ void zero_deg_kernel() {
    int i = blockIdx.x * blockDim.x + threadIdx.x;
    if (i < NN) g_deg[i] = 0;
}

__global__ void count_deg_kernel(const int* __restrict__ ei) {
    int e = blockIdx.x * blockDim.x + threadIdx.x;
    if (e >= ETOT) return;
    int d = (e < EE) ? ei[EE + e] : (e - EE);   // self loop for e >= EE
    atomicAdd(&g_deg[d], 1);
}

__global__ __launch_bounds__(256) void scan1_kernel() {
    int b = blockIdx.x;
    int i = b * 256 + threadIdx.x;
    int v = (i < NN) ? g_deg[i] : 0;
    int lane = threadIdx.x & 31, w = threadIdx.x >> 5;
    int s = v;
    #pragma unroll
    for (int off = 1; off < 32; off <<= 1) {
        int t = __shfl_up_sync(0xffffffffu, s, off);
        if (lane >= off) s += t;
    }
    __shared__ int ws[8];
    if (lane == 31) ws[w] = s;
    __syncthreads();
    if (threadIdx.x == 0) {
        int acc = 0;
        #pragma unroll
        for (int j = 0; j < 8; j++) { int t = ws[j]; ws[j] = acc; acc += t; }
        g_blocksum[b] = acc;
    }
    __syncthreads();
    s += ws[w];
    if (i < NN) g_rowptr[i + 1] = s;
}

__global__ __launch_bounds__(256) void scan2_kernel() {
    int t = threadIdx.x;
    int v = (t < NBLK) ? g_blocksum[t] : 0;
    int lane = t & 31, w = t >> 5;
    int s = v;
    #pragma unroll
    for (int off = 1; off < 32; off <<= 1) {
        int u = __shfl_up_sync(0xffffffffu, s, off);
        if (lane >= off) s += u;
    }
    __shared__ int ws[8];
    if (lane == 31) ws[w] = s;
    __syncthreads();
    if (t == 0) {
        int acc = 0;
        #pragma unroll
        for (int j = 0; j < 8; j++) { int u = ws[j]; ws[j] = acc; acc += u; }
    }
    __syncthreads();
    s += ws[w];
    g_blockoff[t] = s - v;
}

__global__ void scan3_kernel() {
    int i = blockIdx.x * blockDim.x + threadIdx.x;
    if (i >= NN) return;
    int off  = g_blockoff[i >> 8];
    int incl = g_rowptr[i + 1] + off;
    g_rowptr[i + 1] = incl;
    g_cursor[i]     = incl - g_deg[i];
    if (i == 0) g_rowptr[0] = 0;
}

__global__ void scatter_edges_kernel(const int* __restrict__ ei) {
    int e = blockIdx.x * blockDim.x + threadIdx.x;
    if (e >= ETOT) return;
    int s, d;
    if (e < EE) { s = ei[e]; d = ei[EE + e]; }
    else        { s = d = e - EE; }
    int pos = atomicAdd(&g_cursor[d], 1);
    g_csr[pos] = s;
}

// ---------------- fp16 tensor-core GEMM (ldmatrix + m16n8k16) ---------------
// C[M,ncols] = A[M,K] @ B[K,N] (+bias). N mult of 128, K mult of 32.
// 128x128 block tile, BK=32, 8 warps (2x4), warp tile 64x32.
// A,B fp32 in gmem, converted to fp16 during staging (fp16 mantissa == tf32).
// HPB: heads per block-col tile for fused attn-coef epilogue (0 = none).
// HALFOUT: C written fp16 (message buffer); else fp32 + bias.
#define SAH 40    // A smem row stride in halfs (80 B: ldmatrix conflict-free)
#define SBH 136   // B smem row stride in halfs (272 B: conflict-free)

__device__ __forceinline__ void ldm_x4(uint32_t* r, uint32_t addr) {
    asm volatile("ldmatrix.sync.aligned.m8n8.x4.shared.b16 {%0,%1,%2,%3}, [%4];"
                 : "=r"(r[0]), "=r"(r[1]), "=r"(r[2]), "=r"(r[3]) : "r"(addr));
}
__device__ __forceinline__ void ldm_x4_t(uint32_t* r, uint32_t addr) {
    asm volatile("ldmatrix.sync.aligned.m8n8.x4.trans.shared.b16 {%0,%1,%2,%3}, [%4];"
                 : "=r"(r[0]), "=r"(r[1]), "=r"(r[2]), "=r"(r[3]) : "r"(addr));
}
__device__ __forceinline__ void mma_f16(float* c, uint32_t a0, uint32_t a1,
                                        uint32_t a2, uint32_t a3,
                                        uint32_t b0, uint32_t b1) {
    asm volatile(
        "mma.sync.aligned.m16n8k16.row.col.f32.f16.f16.f32 "
        "{%0,%1,%2,%3},{%4,%5,%6,%7},{%8,%9},{%0,%1,%2,%3};\n"
        : "+f"(c[0]), "+f"(c[1]), "+f"(c[2]), "+f"(c[3])
        : "r"(a0), "r"(a1), "r"(a2), "r"(a3), "r"(b0), "r"(b1));
}

template <int HPB, bool HALFOUT>
__global__ __launch_bounds__(256) void gemm_f16_kernel(
    int M, int N, int K,
    const float* __restrict__ A, const float* __restrict__ B,
    float* __restrict__ Cf, __half* __restrict__ Chalf,
    int ldc, int ncols, const float* __restrict__ bias,
    const float* __restrict__ avs, const float* __restrict__ avd,
    float* __restrict__ o_src, float* __restrict__ o_dst)
{
    __shared__ __half As[2][128 * SAH];
    __shared__ __half Bs[2][32 * SBH];
    __shared__ float sm_src[4][128];
    __shared__ float sm_dst[4][128];

    int tid  = threadIdx.x;
    int row0 = blockIdx.y * 128;
    int col0 = blockIdx.x * 128;
    int warp = tid >> 5, lane = tid & 31;
    int wm = warp & 1, wn = warp >> 1;       // 2 x 4 warps -> warp tile 64x32
    int tg = lane >> 2, tig = lane & 3;

    // staging indices
    int ar = tid >> 2,  ac = (tid & 3) * 4;   // A rows {ar, ar+64}, cols {ac, ac+16}
    int br = tid >> 3,  bc = (tid & 7) * 16;  // B row br, cols bc..bc+15

    bool a0ok = (row0 + ar)      < M;
    bool a1ok = (row0 + ar + 64) < M;

    float4 a00, a01, a10, a11, bv0, bv1, bv2, bv3;

    auto ldg_tile = [&](int kt) {
        int kb = kt * 32;
        const float* ap0 = A + (size_t)(row0 + ar) * K + kb + ac;
        const float* ap1 = A + (size_t)(row0 + ar + 64) * K + kb + ac;
        float4 z = make_float4(0.f, 0.f, 0.f, 0.f);
        a00 = a0ok ? *(const float4*)(ap0)      : z;
        a01 = a0ok ? *(const float4*)(ap0 + 16) : z;
        a10 = a1ok ? *(const float4*)(ap1)      : z;
        a11 = a1ok ? *(const float4*)(ap1 + 16) : z;
        const float* bp = B + (size_t)(kb + br) * N + col0 + bc;
        bv0 = *(const float4*)(bp);
        bv1 = *(const float4*)(bp + 4);
        bv2 = *(const float4*)(bp + 8);
        bv3 = *(const float4*)(bp + 12);
    };

    auto sts4 = [](__half* dst, float4 v) {
        __half2* p = (__half2*)dst;
        p[0] = __floats2half2_rn(v.x, v.y);
        p[1] = __floats2half2_rn(v.z, v.w);
    };

    auto sts_tile = [&](int buf) {
        __half* Ab = As[buf];
        __half* Bb = Bs[buf];
        sts4(Ab + ar * SAH + ac,             a00);
        sts4(Ab + ar * SAH + ac + 16,        a01);
        sts4(Ab + (ar + 64) * SAH + ac,      a10);
        sts4(Ab + (ar + 64) * SAH + ac + 16, a11);
        __half* q = Bb + br * SBH + bc;
        sts4(q,      bv0);
        sts4(q + 4,  bv1);
        sts4(q + 8,  bv2);
        sts4(q + 12, bv3);
    };

    float c[4][4][4];
    #pragma unroll
    for (int mi = 0; mi < 4; mi++)
        #pragma unroll
        for (int ni = 0; ni < 4; ni++)
            #pragma unroll
            for (int j = 0; j < 4; j++) c[mi][ni][j] = 0.0f;

    // per-thread ldmatrix lane offsets (bytes)
    uint32_t sa0 = (uint32_t)__cvta_generic_to_shared(As[0]);
    uint32_t sa1 = (uint32_t)__cvta_generic_to_shared(As[1]);
    uint32_t sb0 = (uint32_t)__cvta_generic_to_shared(Bs[0]);
    uint32_t sb1 = (uint32_t)__cvta_generic_to_shared(Bs[1]);
    int la = lane & 15, lh = lane >> 4;
    uint32_t a_lane = (uint32_t)((la * SAH + lh * 8) * 2);
    uint32_t b_lane = (uint32_t)((la * SBH + lh * 8) * 2);

    auto compute = [&](int buf) {
        uint32_t sa = (buf ? sa1 : sa0) + a_lane + (uint32_t)(wm * 64 * SAH * 2);
        uint32_t sb = (buf ? sb1 : sb0) + b_lane + (uint32_t)(wn * 32 * 2);
        #pragma unroll
        for (int ks = 0; ks < 2; ks++) {
            int kk = ks * 16;
            uint32_t af[4][4], bf[2][4];
            #pragma unroll
            for (int mi = 0; mi < 4; mi++)
                ldm_x4(af[mi], sa + (uint32_t)((mi * 16 * SAH + kk) * 2));
            #pragma unroll
            for (int np = 0; np < 2; np++)
                ldm_x4_t(bf[np], sb + (uint32_t)((kk * SBH + np * 16) * 2));
            #pragma unroll
            for (int mi = 0; mi < 4; mi++)
                #pragma unroll
                for (int np = 0; np < 2; np++) {
                    mma_f16(c[mi][np * 2],     af[mi][0], af[mi][1], af[mi][2], af[mi][3],
                            bf[np][0], bf[np][1]);
                    mma_f16(c[mi][np * 2 + 1], af[mi][0], af[mi][1], af[mi][2], af[mi][3],
                            bf[np][2], bf[np][3]);
                }
        }
    };

    int KT = K / 32;
    ldg_tile(0);
    sts_tile(0);
    __syncthreads();
    for (int kt = 0; kt < KT; kt++) {
        int buf = kt & 1;
        bool more = (kt + 1 < KT);
        if (more) ldg_tile(kt + 1);
        compute(buf);
        if (more) sts_tile(buf ^ 1);
        __syncthreads();
    }

    // ---- fused attention-coefficient epilogue ----
    if (HPB > 0) {
        float sa_[4][2], da_[4][2];
        #pragma unroll
        for (int mi = 0; mi < 4; mi++) {
            sa_[mi][0] = sa_[mi][1] = 0.f;
            da_[mi][0] = da_[mi][1] = 0.f;
        }
        #pragma unroll
        for (int ni = 0; ni < 4; ni++) {
            int cl = wn * 32 + ni * 8 + tig * 2;
            float ws0 = avs[col0 + cl], ws1 = avs[col0 + cl + 1];
            float wd0 = avd[col0 + cl], wd1 = avd[col0 + cl + 1];
            #pragma unroll
            for (int mi = 0; mi < 4; mi++) {
                sa_[mi][0] += c[mi][ni][0] * ws0 + c[mi][ni][1] * ws1;
                da_[mi][0] += c[mi][ni][0] * wd0 + c[mi][ni][1] * wd1;
                sa_[mi][1] += c[mi][ni][2] * ws0 + c[mi][ni][3] * ws1;
                da_[mi][1] += c[mi][ni][2] * wd0 + c[mi][ni][3] * wd1;
            }
        }
        #pragma unroll
        for (int mi = 0; mi < 4; mi++)
            #pragma unroll
            for (int p = 0; p < 2; p++) {
                sa_[mi][p] += __shfl_xor_sync(0xffffffffu, sa_[mi][p], 1);
                sa_[mi][p] += __shfl_xor_sync(0xffffffffu, sa_[mi][p], 2);
                da_[mi][p] += __shfl_xor_sync(0xffffffffu, da_[mi][p], 1);
                da_[mi][p] += __shfl_xor_sync(0xffffffffu, da_[mi][p], 2);
            }
        if (tig == 0) {
            #pragma unroll
            for (int mi = 0; mi < 4; mi++) {
                int rl = wm * 64 + mi * 16 + tg;
                sm_src[wn][rl]     = sa_[mi][0];
                sm_src[wn][rl + 8] = sa_[mi][1];
                sm_dst[wn][rl]     = da_[mi][0];
                sm_dst[wn][rl + 8] = da_[mi][1];
            }
        }
        __syncthreads();
        if (tid < 128) {
            int r = row0 + tid;
            if (r < M) {
                if (HPB == 1) {
                    float s = sm_src[0][tid] + sm_src[1][tid] + sm_src[2][tid] + sm_src[3][tid];
                    float d = sm_dst[0][tid] + sm_dst[1][tid] + sm_dst[2][tid] + sm_dst[3][tid];
                    o_src[r * HH + blockIdx.x] = s;
                    o_dst[r * HH + blockIdx.x] = d;
                } else {
                    float s0 = sm_src[0][tid] + sm_src[1][tid];
                    float s1 = sm_src[2][tid] + sm_src[3][tid];
                    float d0 = sm_dst[0][tid] + sm_dst[1][tid];
                    float d1 = sm_dst[2][tid] + sm_dst[3][tid];
                    int hb = blockIdx.x * 2;
                    o_src[r * HH + hb]     = s0;
                    o_src[r * HH + hb + 1] = s1;
                    o_dst[r * HH + hb]     = d0;
                    o_dst[r * HH + hb + 1] = d1;
                }
            }
        }
    }

    // ---- C write ----
    #pragma unroll
    for (int mi = 0; mi < 4; mi++) {
        int r = row0 + wm * 64 + mi * 16 + tg;
        #pragma unroll
        for (int ni = 0; ni < 4; ni++) {
            int cc = col0 + wn * 32 + ni * 8 + tig * 2;
            if (cc >= ncols) continue;
            if (HALFOUT) {
                if (r < M)
                    *(__half2*)(Chalf + (size_t)r * ldc + cc) =
                        __floats2half2_rn(c[mi][ni][0], c[mi][ni][1]);
                if (r + 8 < M)
                    *(__half2*)(Chalf + (size_t)(r + 8) * ldc + cc) =
                        __floats2half2_rn(c[mi][ni][2], c[mi][ni][3]);
            } else {
                float b0 = bias ? bias[cc]     : 0.f;
                float b1 = bias ? bias[cc + 1] : 0.f;
                if (r < M) {
                    Cf[(size_t)r * ldc + cc]     = c[mi][ni][0] + b0;
                    Cf[(size_t)r * ldc + cc + 1] = c[mi][ni][1] + b1;
                }
                if (r + 8 < M) {
                    Cf[(size_t)(r + 8) * ldc + cc]     = c[mi][ni][2] + b0;
                    Cf[(size_t)(r + 8) * ldc + cc + 1] = c[mi][ni][3] + b1;
                }
            }
        }
    }
}

// Pad Wf [CH2, NCLS] -> g_Wfpad [CH2, 128] with zeros
__global__ void pad_wf_kernel(const float* __restrict__ Wf) {
    int i = blockIdx.x * blockDim.x + threadIdx.x;
    if (i >= CH2 * 128) return;
    int r = i >> 7, cc = i & 127;
    g_Wfpad[i] = (cc < NCLS) ? Wf[r * NCLS + cc] : 0.f;
}

// ---------------- GAT softmax + aggregation (one block per dst node) --------
#define DCAP 512
template <int CH>
__global__ __launch_bounds__(128) void gat_agg_kernel(
    const __half* __restrict__ h,
    const float* __restrict__ asrc, const float* __restrict__ adst,
    const float* __restrict__ bias, float* __restrict__ out)
{
    constexpr int VEC = CH / 128;             // 4 (layer1) or 2 (layer2)
    __shared__ int   ssrc[DCAP];
    __shared__ float sexp[DCAP * HH];
    __shared__ float red[4][HH];

    int d    = blockIdx.x;
    int tid  = threadIdx.x;
    int lane = tid & 31, warp = tid >> 5;
    int s0   = g_rowptr[d];
    int deg  = g_rowptr[d + 1] - s0;

    float4 ad4 = *(const float4*)&adst[d * HH];

    float sm[HH] = {0.f, 0.f, 0.f, 0.f};
    if (deg <= DCAP) {
        for (int j = tid; j < deg; j += 128) {
            int s = g_csr[s0 + j];
            ssrc[j] = s;
            float4 a = *(const float4*)&asrc[s * HH];
            float e0 = a.x + ad4.x; e0 = (e0 > 0.f) ? e0 : SLOPE * e0; e0 = __expf(e0);
            float e1 = a.y + ad4.y; e1 = (e1 > 0.f) ? e1 : SLOPE * e1; e1 = __expf(e1);
            float e2 = a.z + ad4.z; e2 = (e2 > 0.f) ? e2 : SLOPE * e2; e2 = __expf(e2);
            float e3 = a.w + ad4.w; e3 = (e3 > 0.f) ? e3 : SLOPE * e3; e3 = __expf(e3);
            sexp[j * HH + 0] = e0; sexp[j * HH + 1] = e1;
            sexp[j * HH + 2] = e2; sexp[j * HH + 3] = e3;
            sm[0] += e0; sm[1] += e1; sm[2] += e2; sm[3] += e3;
        }
    } else {
        for (int j = tid; j < deg; j += 128) {
            int s = g_csr[s0 + j];
            float4 a = *(const float4*)&asrc[s * HH];
            float e0 = a.x + ad4.x; e0 = (e0 > 0.f) ? e0 : SLOPE * e0;
            float e1 = a.y + ad4.y; e1 = (e1 > 0.f) ? e1 : SLOPE * e1;
            float e2 = a.z + ad4.z; e2 = (e2 > 0.f) ? e2 : SLOPE * e2;
            float e3 = a.w + ad4.w; e3 = (e3 > 0.f) ? e3 : SLOPE * e3;
            sm[0] += __expf(e0); sm[1] += __expf(e1);
            sm[2] += __expf(e2); sm[3] += __expf(e3);
        }
    }
    #pragma unroll
    for (int hh = 0; hh < HH; hh++)
        #pragma unroll
        for (int off = 16; off > 0; off >>= 1)
            sm[hh] += __shfl_xor_sync(0xffffffffu, sm[hh], off);
    if (lane == 0)
        #pragma unroll
        for (int hh = 0; hh < HH; hh++) red[warp][hh] = sm[hh];
    __syncthreads();   // also publishes ssrc/sexp

    int head = tid >> 5;
    float ih = 1.0f / (red[0][head] + red[1][head] + red[2][head] + red[3][head] + 1e-16f);

    float acc[VEC];
    #pragma unroll
    for (int j = 0; j < VEC; j++) acc[j] = 0.f;

    const int hoff = tid * (VEC / 2);   // __half2 offset within row

    if (deg <= DCAP) {
        int j = 0;
        for (; j + 4 <= deg; j += 4) {
            int sA = ssrc[j], sB = ssrc[j + 1], sC = ssrc[j + 2], sD = ssrc[j + 3];
            float eA = sexp[(j    ) * HH + head];
            float eB = sexp[(j + 1) * HH + head];
            float eC = sexp[(j + 2) * HH + head];
            float eD = sexp[(j + 3) * HH + head];
            const __half2* pA = (const __half2*)(h + (size_t)sA * CH) + hoff;
            const __half2* pB = (const __half2*)(h + (size_t)sB * CH) + hoff;
            const __half2* pC = (const __half2*)(h + (size_t)sC * CH) + hoff;
            const __half2* pD = (const __half2*)(h + (size_t)sD * CH) + hoff;
            if (VEC == 4) {
                __half2 a0 = pA[0], a1 = pA[1];
                __half2 b0 = pB[0], b1 = pB[1];
                __half2 c0 = pC[0], c1 = pC[1];
                __half2 d0 = pD[0], d1 = pD[1];
                float2 f;
                f = __half22float2(a0); acc[0] += eA * f.x; acc[1] += eA * f.y;
                f = __half22float2(a1); acc[2] += eA * f.x; acc[3] += eA * f.y;
                f = __half22float2(b0); acc[0] += eB * f.x; acc[1] += eB * f.y;
                f = __half22float2(b1); acc[2] += eB * f.x; acc[3] += eB * f.y;
                f = __half22float2(c0); acc[0] += eC * f.x; acc[1] += eC * f.y;
                f = __half22float2(c1); acc[2] += eC * f.x; acc[3] += eC * f.y;
                f = __half22float2(d0); acc[0] += eD * f.x; acc[1] += eD * f.y;
                f = __half22float2(d1); acc[2] += eD * f.x; acc[3] += eD * f.y;
            } else {
                __half2 a0 = pA[0], b0 = pB[0], c0 = pC[0], d0 = pD[0];
                float2 f;
                f = __half22float2(a0); acc[0] += eA * f.x; acc[1] += eA * f.y;
                f = __half22float2(b0); acc[0] += eB * f.x; acc[1] += eB * f.y;
                f = __half22float2(c0); acc[0] += eC * f.x; acc[1] += eC * f.y;
                f = __half22float2(d0); acc[0] += eD * f.x; acc[1] += eD * f.y;
            }
        }
        for (; j < deg; j++) {
            int s = ssrc[j];
            float e = sexp[j * HH + head];
            const __half2* p = (const __half2*)(h + (size_t)s * CH) + hoff;
            #pragma unroll
            for (int q = 0; q < VEC / 2; q++) {
                float2 f = __half22float2(p[q]);
                acc[q * 2]     += e * f.x;
                acc[q * 2 + 1] += e * f.y;
            }
        }
    } else {
        for (int c0 = 0; c0 < deg; c0 += DCAP) {
            int cn = min(DCAP, deg - c0);
            __syncthreads();
            for (int j = tid; j < cn; j += 128) {
                int s = g_csr[s0 + c0 + j];
                ssrc[j] = s;
                float4 a = *(const float4*)&asrc[s * HH];
                float e0 = a.x + ad4.x; e0 = (e0 > 0.f) ? e0 : SLOPE * e0;
                float e1 = a.y + ad4.y; e1 = (e1 > 0.f) ? e1 : SLOPE * e1;
                float e2 = a.z + ad4.z; e2 = (e2 > 0.f) ? e2 : SLOPE * e2;
                float e3 = a.w + ad4.w; e3 = (e3 > 0.f) ? e3 : SLOPE * e3;
                sexp[j * HH + 0] = __expf(e0); sexp[j * HH + 1] = __expf(e1);
                sexp[j * HH + 2] = __expf(e2); sexp[j * HH + 3] = __expf(e3);
            }
            __syncthreads();
            for (int j = 0; j < cn; j++) {
                int s = ssrc[j];
                float e = sexp[j * HH + head];
                const __half2* p = (const __half2*)(h + (size_t)s * CH) + hoff;
                #pragma unroll
                for (int q = 0; q < VEC / 2; q++) {
                    float2 f = __half22float2(p[q]);
                    acc[q * 2]     += e * f.x;
                    acc[q * 2 + 1] += e * f.y;
                }
            }
        }
    }

    #pragma unroll
    for (int j = 0; j < VEC; j++) {
        float v = acc[j] * ih + bias[tid * VEC + j];
        out[(size_t)d * CH + tid * VEC + j] = (v > 0.f) ? v : expm1f(v);
    }
}

// ---------------- launch ----------------------------------------------------
extern "C" void kernel_launch(void* const* d_in, const int* in_sizes, int n_in,
                              void* d_out, int out_size)
{
    const float* x   = (const float*)d_in[0];
    const int*   ei  = (const int*)  d_in[1];
    const float* W1  = (const float*)d_in[2];
    const float* as1 = (const float*)d_in[3];
    const float* ad1 = (const float*)d_in[4];
    const float* b1  = (const float*)d_in[5];
    const float* W2  = (const float*)d_in[6];
    const float* as2 = (const float*)d_in[7];
    const float* ad2 = (const float*)d_in[8];
    const float* b2  = (const float*)d_in[9];
    const float* Wf  = (const float*)d_in[10];
    const float* bf  = (const float*)d_in[11];
    float* out = (float*)d_out;

    __half *h1h, *h2h;
    float *g1, *g2, *pas, *pad, *wfp;
    cudaGetSymbolAddress((void**)&h1h, g_h1h);
    cudaGetSymbolAddress((void**)&h2h, g_h2h);
    cudaGetSymbolAddress((void**)&g1,  g_g1);
    cudaGetSymbolAddress((void**)&g2,  g_g2);
    cudaGetSymbolAddress((void**)&pas, g_asrc);
    cudaGetSymbolAddress((void**)&pad, g_adst);
    cudaGetSymbolAddress((void**)&wfp, g_Wfpad);

    int grid_y = (NN + 127) / 128;   // 391

    // Launch order keeps GEMM1 as the 4th launch (ncu fixed-skip capture).
    zero_deg_kernel<<<(NN + 255) / 256, 256>>>();
    count_deg_kernel<<<(ETOT + 255) / 256, 256>>>(ei);
    pad_wf_kernel<<<(CH2 * 128 + 255) / 256, 256>>>(Wf);

    // Layer 1 GEMM (+ fused attn coefs, fp16 h out)
    gemm_f16_kernel<1, true><<<dim3(CH1 / 128, grid_y), 256>>>(
        NN, CH1, FIN, x, W1, (float*)nullptr, h1h, CH1, CH1, (const float*)nullptr,
        as1, ad1, pas, pad);

    // CSR build
    scan1_kernel<<<NBLK, 256>>>();
    scan2_kernel<<<1, 256>>>();
    scan3_kernel<<<NBLK, 256>>>();
    scatter_edges_kernel<<<(ETOT + 255) / 256, 256>>>(ei);

    gat_agg_kernel<CH1><<<NN, 128>>>(h1h, pas, pad, b1, g1);

    // Layer 2
    gemm_f16_kernel<2, true><<<dim3(CH2 / 128, grid_y), 256>>>(
        NN, CH2, CH1, g1, W2, (float*)nullptr, h2h, CH2, CH2, (const float*)nullptr,
        as2, ad2, pas, pad);
    gat_agg_kernel<CH2><<<NN, 128>>>(h2h, pas, pad, b2, g2);

    // Final classifier as padded fp16 GEMM: out[N,50] = g2 @ Wfpad + bf
    gemm_f16_kernel<0, false><<<dim3(1, grid_y), 256>>>(
        NN, 128, CH2, g2, wfp, out, (__half*)nullptr, NCLS, NCLS, bf,
        (const float*)nullptr, (const float*)nullptr,
        (float*)nullptr, (float*)nullptr);
}

// round 8
// speedup vs baseline: 3.1865x; 1.1038x over previous
#include <cuda_runtime.h>
#include <cuda_fp16.h>
#include <math.h>
#include <stdint.h>

// Problem constants (fixed by the dataset)
#define NN    50000
#define EE    800000
#define ETOT  850000        // EE + NN self loops
#define FIN   256
#define HH    4
#define CC1   128
#define CC2   64
#define CH1   512           // HH*CC1
#define CH2   256           // HH*CC2
#define NCLS  50
#define SLOPE 0.2f
#define NBLK  ((NN + 255) / 256)

// ---------------- scratch (device globals; no allocations allowed) ----------
__device__ __half g_xh [NN * FIN];    // x   in fp16 (GEMM1 A)
__device__ __half g_W1h[FIN * CH1];   // W1  fp16
__device__ __half g_W2h[CH1 * CH2];   // W2  fp16
__device__ __half g_Wfh[CH2 * 128];   // Wf  fp16, zero-padded to 128 cols
__device__ __half g_h1h[NN * CH1];    // x @ W1  (messages, fp16)
__device__ __half g_h2h[NN * CH2];    // g1 @ W2 (messages, fp16)
__device__ __half g_g1h[NN * CH1];    // elu(agg1 + b1), fp16 (GEMM2 A)
__device__ __half g_g2h[NN * CH2];    // elu(agg2 + b2), fp16 (GEMM3 A)
__device__ float g_asrc[NN * HH];
__device__ float g_adst[NN * HH];
__device__ int   g_deg[NN];
__device__ int   g_rowptr[NN + 1];
__device__ int   g_cursor[NN];
__device__ int   g_csr[ETOT];
__device__ int   g_blocksum[256];
__device__ int   g_blockoff[256];

// ---------------- CSR construction ------------------------------------------
__global__ void zero_deg_kernel() {
    int i = blockIdx.x * blockDim.x + threadIdx.x;
    if (i < NN) g_deg[i] = 0;
}

__global__ void count_deg_kernel(const int* __restrict__ ei) {
    int e = blockIdx.x * blockDim.x + threadIdx.x;
    if (e >= ETOT) return;
    int d = (e < EE) ? ei[EE + e] : (e - EE);   // self loop for e >= EE
    atomicAdd(&g_deg[d], 1);
}

__global__ __launch_bounds__(256) void scan1_kernel() {
    int b = blockIdx.x;
    int i = b * 256 + threadIdx.x;
    int v = (i < NN) ? g_deg[i] : 0;
    int lane = threadIdx.x & 31, w = threadIdx.x >> 5;
    int s = v;
    #pragma unroll
    for (int off = 1; off < 32; off <<= 1) {
        int t = __shfl_up_sync(0xffffffffu, s, off);
        if (lane >= off) s += t;
    }
    __shared__ int ws[8];
    if (lane == 31) ws[w] = s;
    __syncthreads();
    if (threadIdx.x == 0) {
        int acc = 0;
        #pragma unroll
        for (int j = 0; j < 8; j++) { int t = ws[j]; ws[j] = acc; acc += t; }
        g_blocksum[b] = acc;
    }
    __syncthreads();
    s += ws[w];
    if (i < NN) g_rowptr[i + 1] = s;
}

__global__ __launch_bounds__(256) void scan2_kernel() {
    int t = threadIdx.x;
    int v = (t < NBLK) ? g_blocksum[t] : 0;
    int lane = t & 31, w = t >> 5;
    int s = v;
    #pragma unroll
    for (int off = 1; off < 32; off <<= 1) {
        int u = __shfl_up_sync(0xffffffffu, s, off);
        if (lane >= off) s += u;
    }
    __shared__ int ws[8];
    if (lane == 31) ws[w] = s;
    __syncthreads();
    if (t == 0) {
        int acc = 0;
        #pragma unroll
        for (int j = 0; j < 8; j++) { int u = ws[j]; ws[j] = acc; acc += u; }
    }
    __syncthreads();
    s += ws[w];
    g_blockoff[t] = s - v;
}

__global__ void scan3_kernel() {
    int i = blockIdx.x * blockDim.x + threadIdx.x;
    if (i >= NN) return;
    int off  = g_blockoff[i >> 8];
    int incl = g_rowptr[i + 1] + off;
    g_rowptr[i + 1] = incl;
    g_cursor[i]     = incl - g_deg[i];
    if (i == 0) g_rowptr[0] = 0;
}

__global__ void scatter_edges_kernel(const int* __restrict__ ei) {
    int e = blockIdx.x * blockDim.x + threadIdx.x;
    if (e >= ETOT) return;
    int s, d;
    if (e < EE) { s = ei[e]; d = ei[EE + e]; }
    else        { s = d = e - EE; }
    int pos = atomicAdd(&g_cursor[d], 1);
    g_csr[pos] = s;
}

// ---------------- fp32 -> fp16 input conversion (one kernel) ----------------
__global__ __launch_bounds__(256) void convert_inputs_kernel(
    const float* __restrict__ x, const float* __restrict__ W1,
    const float* __restrict__ W2, const float* __restrict__ Wf)
{
    int i = blockIdx.x * blockDim.x + threadIdx.x;   // float4 index for x
    if (i < NN * FIN / 4) {
        float4 v = *(const float4*)(x + i * 4);
        __half2* p = (__half2*)(g_xh + i * 4);
        p[0] = __floats2half2_rn(v.x, v.y);
        p[1] = __floats2half2_rn(v.z, v.w);
    }
    if (i < FIN * CH1 / 4) {
        float4 v = *(const float4*)(W1 + i * 4);
        __half2* p = (__half2*)(g_W1h + i * 4);
        p[0] = __floats2half2_rn(v.x, v.y);
        p[1] = __floats2half2_rn(v.z, v.w);
    }
    if (i < CH1 * CH2 / 4) {
        float4 v = *(const float4*)(W2 + i * 4);
        __half2* p = (__half2*)(g_W2h + i * 4);
        p[0] = __floats2half2_rn(v.x, v.y);
        p[1] = __floats2half2_rn(v.z, v.w);
    }
    if (i < CH2 * 128) {
        int r = i >> 7, cc = i & 127;
        g_Wfh[i] = __float2half((cc < NCLS) ? Wf[r * NCLS + cc] : 0.f);
    }
}

// ---------------- fp16 tensor-core GEMM: 256x128 tile, cp.async -------------
// C[M,ncols] = A[M,K] @ B[K,N] (+bias). A,B fp16 in gmem. N mult of 128,
// K mult of 32. 8 warps as 4x2 -> warp tile 64x64 (m16n8k16).
// HPB: heads per 128-col tile for fused attn-coef epilogue (0 = none).
// HALFOUT: C written fp16; else fp32 + bias.
#define SAH 40     // A smem row stride (halfs): 80 B, ldmatrix conflict-free
#define SBH 136    // B smem row stride (halfs): 272 B, conflict-free
#define A_BUF (256 * SAH)
#define B_BUF (32 * SBH)
#define GEMM_SMEM ((2 * A_BUF + 2 * B_BUF) * 2)   // bytes = 58368

__device__ __forceinline__ void ldm_x4(uint32_t* r, uint32_t addr) {
    asm volatile("ldmatrix.sync.aligned.m8n8.x4.shared.b16 {%0,%1,%2,%3}, [%4];"
                 : "=r"(r[0]), "=r"(r[1]), "=r"(r[2]), "=r"(r[3]) : "r"(addr));
}
__device__ __forceinline__ void ldm_x4_t(uint32_t* r, uint32_t addr) {
    asm volatile("ldmatrix.sync.aligned.m8n8.x4.trans.shared.b16 {%0,%1,%2,%3}, [%4];"
                 : "=r"(r[0]), "=r"(r[1]), "=r"(r[2]), "=r"(r[3]) : "r"(addr));
}
__device__ __forceinline__ void mma_f16(float* c, uint32_t a0, uint32_t a1,
                                        uint32_t a2, uint32_t a3,
                                        uint32_t b0, uint32_t b1) {
    asm volatile(
        "mma.sync.aligned.m16n8k16.row.col.f32.f16.f16.f32 "
        "{%0,%1,%2,%3},{%4,%5,%6,%7},{%8,%9},{%0,%1,%2,%3};\n"
        : "+f"(c[0]), "+f"(c[1]), "+f"(c[2]), "+f"(c[3])
        : "r"(a0), "r"(a1), "r"(a2), "r"(a3), "r"(b0), "r"(b1));
}
__device__ __forceinline__ void cp16(uint32_t dst, const void* src, bool ok) {
    int sz = ok ? 16 : 0;
    asm volatile("cp.async.ca.shared.global [%0], [%1], 16, %2;"
                 :: "r"(dst), "l"(src), "r"(sz));
}

template <int HPB, bool HALFOUT>
__global__ __launch_bounds__(256) void gemm_f16_kernel(
    int M, int N, int K,
    const __half* __restrict__ A, const __half* __restrict__ B,
    float* __restrict__ Cf, __half* __restrict__ Chalf,
    int ldc, int ncols, const float* __restrict__ bias,
    const float* __restrict__ avs, const float* __restrict__ avd,
    float* __restrict__ o_src, float* __restrict__ o_dst)
{
    extern __shared__ __half smem[];
    uint32_t smem_u32 = (uint32_t)__cvta_generic_to_shared(smem);

    int tid  = threadIdx.x;
    int row0 = blockIdx.y * 256;
    int col0 = blockIdx.x * 128;
    int warp = tid >> 5, lane = tid & 31;
    int wm = warp >> 1, wn = warp & 1;       // 4x2 warps -> warp tile 64x64
    int tg = lane >> 2, tig = lane & 3;

    bool aok = (row0 + tid) < M;

    auto issue = [&](int kt, int buf) {
        // A: row = tid, 4 x 16B chunks
        const __half* asrc = A + (size_t)(row0 + tid) * K + kt * 32;
        uint32_t adst = smem_u32 + (uint32_t)((buf * A_BUF + tid * SAH) * 2);
        #pragma unroll
        for (int i = 0; i < 4; i++)
            cp16(adst + i * 16, asrc + i * 8, aok);
        // B: row = tid>>3, 2 x 16B chunks
        int brow = tid >> 3, bch = (tid & 7) * 2;
        const __half* bsrc = B + (size_t)(kt * 32 + brow) * N + col0 + bch * 8;
        uint32_t bdst = smem_u32 +
            (uint32_t)((2 * A_BUF + buf * B_BUF + brow * SBH + bch * 8) * 2);
        cp16(bdst,      bsrc,     true);
        cp16(bdst + 16, bsrc + 8, true);
        asm volatile("cp.async.commit_group;");
    };

    float c[4][8][4];
    #pragma unroll
    for (int mi = 0; mi < 4; mi++)
        #pragma unroll
        for (int ni = 0; ni < 8; ni++)
            #pragma unroll
            for (int j = 0; j < 4; j++) c[mi][ni][j] = 0.0f;

    int la = lane & 15, lh = lane >> 4;
    uint32_t a_lane = (uint32_t)((la * SAH + lh * 8) * 2);
    uint32_t b_lane = (uint32_t)((la * SBH + lh * 8) * 2);

    auto compute = [&](int buf) {
        uint32_t sa = smem_u32 + (uint32_t)(buf * A_BUF * 2) + a_lane
                    + (uint32_t)(wm * 64 * SAH * 2);
        uint32_t sb = smem_u32 + (uint32_t)((2 * A_BUF + buf * B_BUF) * 2) + b_lane
                    + (uint32_t)(wn * 64 * 2);
        #pragma unroll
        for (int ks = 0; ks < 2; ks++) {
            int kk = ks * 16;
            uint32_t af[4][4], bf[4][4];
            #pragma unroll
            for (int mi = 0; mi < 4; mi++)
                ldm_x4(af[mi], sa + (uint32_t)((mi * 16 * SAH + kk) * 2));
            #pragma unroll
            for (int np = 0; np < 4; np++)
                ldm_x4_t(bf[np], sb + (uint32_t)((kk * SBH + np * 16) * 2));
            #pragma unroll
            for (int mi = 0; mi < 4; mi++)
                #pragma unroll
                for (int np = 0; np < 4; np++) {
                    mma_f16(c[mi][np * 2],     af[mi][0], af[mi][1], af[mi][2], af[mi][3],
                            bf[np][0], bf[np][1]);
                    mma_f16(c[mi][np * 2 + 1], af[mi][0], af[mi][1], af[mi][2], af[mi][3],
                            bf[np][2], bf[np][3]);
                }
        }
    };

    int KT = K / 32;
    issue(0, 0);
    for (int kt = 0; kt < KT; kt++) {
        int buf = kt & 1;
        if (kt + 1 < KT) {
            issue(kt + 1, buf ^ 1);
            asm volatile("cp.async.wait_group 1;");
        } else {
            asm volatile("cp.async.wait_group 0;");
        }
        __syncthreads();
        compute(buf);
        __syncthreads();
    }

    // ---- fused attention-coefficient epilogue (overlay dead smem) ----
    if (HPB > 0) {
        float* sm_src = (float*)smem;          // [2][256]
        float* sm_dst = sm_src + 512;          // [2][256]
        float sa_[4][2], da_[4][2];
        #pragma unroll
        for (int mi = 0; mi < 4; mi++) {
            sa_[mi][0] = sa_[mi][1] = 0.f;
            da_[mi][0] = da_[mi][1] = 0.f;
        }
        #pragma unroll
        for (int ni = 0; ni < 8; ni++) {
            int cl = wn * 64 + ni * 8 + tig * 2;
            float ws0 = avs[col0 + cl], ws1 = avs[col0 + cl + 1];
            float wd0 = avd[col0 + cl], wd1 = avd[col0 + cl + 1];
            #pragma unroll
            for (int mi = 0; mi < 4; mi++) {
                sa_[mi][0] += c[mi][ni][0] * ws0 + c[mi][ni][1] * ws1;
                da_[mi][0] += c[mi][ni][0] * wd0 + c[mi][ni][1] * wd1;
                sa_[mi][1] += c[mi][ni][2] * ws0 + c[mi][ni][3] * ws1;
                da_[mi][1] += c[mi][ni][2] * wd0 + c[mi][ni][3] * wd1;
            }
        }
        #pragma unroll
        for (int mi = 0; mi < 4; mi++)
            #pragma unroll
            for (int p = 0; p < 2; p++) {
                sa_[mi][p] += __shfl_xor_sync(0xffffffffu, sa_[mi][p], 1);
                sa_[mi][p] += __shfl_xor_sync(0xffffffffu, sa_[mi][p], 2);
                da_[mi][p] += __shfl_xor_sync(0xffffffffu, da_[mi][p], 1);
                da_[mi][p] += __shfl_xor_sync(0xffffffffu, da_[mi][p], 2);
            }
        if (tig == 0) {
            #pragma unroll
            for (int mi = 0; mi < 4; mi++) {
                int rl = wm * 64 + mi * 16 + tg;
                sm_src[wn * 256 + rl]     = sa_[mi][0];
                sm_src[wn * 256 + rl + 8] = sa_[mi][1];
                sm_dst[wn * 256 + rl]     = da_[mi][0];
                sm_dst[wn * 256 + rl + 8] = da_[mi][1];
            }
        }
        __syncthreads();
        {
            int r = row0 + tid;
            if (r < M) {
                if (HPB == 1) {
                    o_src[r * HH + blockIdx.x] = sm_src[tid] + sm_src[256 + tid];
                    o_dst[r * HH + blockIdx.x] = sm_dst[tid] + sm_dst[256 + tid];
                } else {
                    int hb = blockIdx.x * 2;
                    o_src[r * HH + hb]     = sm_src[tid];
                    o_src[r * HH + hb + 1] = sm_src[256 + tid];
                    o_dst[r * HH + hb]     = sm_dst[tid];
                    o_dst[r * HH + hb + 1] = sm_dst[256 + tid];
                }
            }
        }
    }

    // ---- C write ----
    #pragma unroll
    for (int mi = 0; mi < 4; mi++) {
        int r = row0 + wm * 64 + mi * 16 + tg;
        #pragma unroll
        for (int ni = 0; ni < 8; ni++) {
            int cc = col0 + wn * 64 + ni * 8 + tig * 2;
            if (cc >= ncols) continue;
            if (HALFOUT) {
                if (r < M)
                    *(__half2*)(Chalf + (size_t)r * ldc + cc) =
                        __floats2half2_rn(c[mi][ni][0], c[mi][ni][1]);
                if (r + 8 < M)
                    *(__half2*)(Chalf + (size_t)(r + 8) * ldc + cc) =
                        __floats2half2_rn(c[mi][ni][2], c[mi][ni][3]);
            } else {
                float b0 = bias ? bias[cc]     : 0.f;
                float b1 = bias ? bias[cc + 1] : 0.f;
                if (r < M) {
                    Cf[(size_t)r * ldc + cc]     = c[mi][ni][0] + b0;
                    Cf[(size_t)r * ldc + cc + 1] = c[mi][ni][1] + b1;
                }
                if (r + 8 < M) {
                    Cf[(size_t)(r + 8) * ldc + cc]     = c[mi][ni][2] + b0;
                    Cf[(size_t)(r + 8) * ldc + cc + 1] = c[mi][ni][3] + b1;
                }
            }
        }
    }
}

// ---------------- GAT softmax + aggregation (one block per dst node) --------
// out (fp16) = elu( softmax-weighted sum of fp16 messages + bias )
#define DCAP 512
template <int CH>
__global__ __launch_bounds__(128) void gat_agg_kernel(
    const __half* __restrict__ h,
    const float* __restrict__ asrc, const float* __restrict__ adst,
    const float* __restrict__ bias, __half* __restrict__ out)
{
    constexpr int VEC = CH / 128;             // 4 (layer1) or 2 (layer2)
    __shared__ int   ssrc[DCAP];
    __shared__ float sexp[DCAP * HH];
    __shared__ float red[4][HH];

    int d    = blockIdx.x;
    int tid  = threadIdx.x;
    int lane = tid & 31, warp = tid >> 5;
    int s0   = g_rowptr[d];
    int deg  = g_rowptr[d + 1] - s0;

    float4 ad4 = *(const float4*)&adst[d * HH];

    float sm[HH] = {0.f, 0.f, 0.f, 0.f};
    if (deg <= DCAP) {
        for (int j = tid; j < deg; j += 128) {
            int s = g_csr[s0 + j];
            ssrc[j] = s;
            float4 a = *(const float4*)&asrc[s * HH];
            float e0 = a.x + ad4.x; e0 = (e0 > 0.f) ? e0 : SLOPE * e0; e0 = __expf(e0);
            float e1 = a.y + ad4.y; e1 = (e1 > 0.f) ? e1 : SLOPE * e1; e1 = __expf(e1);
            float e2 = a.z + ad4.z; e2 = (e2 > 0.f) ? e2 : SLOPE * e2; e2 = __expf(e2);
            float e3 = a.w + ad4.w; e3 = (e3 > 0.f) ? e3 : SLOPE * e3; e3 = __expf(e3);
            sexp[j * HH + 0] = e0; sexp[j * HH + 1] = e1;
            sexp[j * HH + 2] = e2; sexp[j * HH + 3] = e3;
            sm[0] += e0; sm[1] += e1; sm[2] += e2; sm[3] += e3;
        }
    } else {
        for (int j = tid; j < deg; j += 128) {
            int s = g_csr[s0 + j];
            float4 a = *(const float4*)&asrc[s * HH];
            float e0 = a.x + ad4.x; e0 = (e0 > 0.f) ? e0 : SLOPE * e0;
            float e1 = a.y + ad4.y; e1 = (e1 > 0.f) ? e1 : SLOPE * e1;
            float e2 = a.z + ad4.z; e2 = (e2 > 0.f) ? e2 : SLOPE * e2;
            float e3 = a.w + ad4.w; e3 = (e3 > 0.f) ? e3 : SLOPE * e3;
            sm[0] += __expf(e0); sm[1] += __expf(e1);
            sm[2] += __expf(e2); sm[3] += __expf(e3);
        }
    }
    #pragma unroll
    for (int hh = 0; hh < HH; hh++)
        #pragma unroll
        for (int off = 16; off > 0; off >>= 1)
            sm[hh] += __shfl_xor_sync(0xffffffffu, sm[hh], off);
    if (lane == 0)
        #pragma unroll
        for (int hh = 0; hh < HH; hh++) red[warp][hh] = sm[hh];
    __syncthreads();   // also publishes ssrc/sexp

    int head = tid >> 5;
    float ih = 1.0f / (red[0][head] + red[1][head] + red[2][head] + red[3][head] + 1e-16f);

    float acc[VEC];
    #pragma unroll
    for (int j = 0; j < VEC; j++) acc[j] = 0.f;

    const int hoff = tid * (VEC / 2);   // __half2 offset within row

    if (deg <= DCAP) {
        int j = 0;
        for (; j + 4 <= deg; j += 4) {
            int sA = ssrc[j], sB = ssrc[j + 1], sC = ssrc[j + 2], sD = ssrc[j + 3];
            float eA = sexp[(j    ) * HH + head];
            float eB = sexp[(j + 1) * HH + head];
            float eC = sexp[(j + 2) * HH + head];
            float eD = sexp[(j + 3) * HH + head];
            const __half2* pA = (const __half2*)(h + (size_t)sA * CH) + hoff;
            const __half2* pB = (const __half2*)(h + (size_t)sB * CH) + hoff;
            const __half2* pC = (const __half2*)(h + (size_t)sC * CH) + hoff;
            const __half2* pD = (const __half2*)(h + (size_t)sD * CH) + hoff;
            if (VEC == 4) {
                __half2 a0 = pA[0], a1 = pA[1];
                __half2 b0 = pB[0], b1 = pB[1];
                __half2 c0 = pC[0], c1 = pC[1];
                __half2 d0 = pD[0], d1 = pD[1];
                float2 f;
                f = __half22float2(a0); acc[0] += eA * f.x; acc[1] += eA * f.y;
                f = __half22float2(a1); acc[2] += eA * f.x; acc[3] += eA * f.y;
                f = __half22float2(b0); acc[0] += eB * f.x; acc[1] += eB * f.y;
                f = __half22float2(b1); acc[2] += eB * f.x; acc[3] += eB * f.y;
                f = __half22float2(c0); acc[0] += eC * f.x; acc[1] += eC * f.y;
                f = __half22float2(c1); acc[2] += eC * f.x; acc[3] += eC * f.y;
                f = __half22float2(d0); acc[0] += eD * f.x; acc[1] += eD * f.y;
                f = __half22float2(d1); acc[2] += eD * f.x; acc[3] += eD * f.y;
            } else {
                __half2 a0 = pA[0], b0 = pB[0], c0 = pC[0], d0 = pD[0];
                float2 f;
                f = __half22float2(a0); acc[0] += eA * f.x; acc[1] += eA * f.y;
                f = __half22float2(b0); acc[0] += eB * f.x; acc[1] += eB * f.y;
                f = __half22float2(c0); acc[0] += eC * f.x; acc[1] += eC * f.y;
                f = __half22float2(d0); acc[0] += eD * f.x; acc[1] += eD * f.y;
            }
        }
        for (; j < deg; j++) {
            int s = ssrc[j];
            float e = sexp[j * HH + head];
            const __half2* p = (const __half2*)(h + (size_t)s * CH) + hoff;
            #pragma unroll
            for (int q = 0; q < VEC / 2; q++) {
                float2 f = __half22float2(p[q]);
                acc[q * 2]     += e * f.x;
                acc[q * 2 + 1] += e * f.y;
            }
        }
    } else {
        for (int c0 = 0; c0 < deg; c0 += DCAP) {
            int cn = min(DCAP, deg - c0);
            __syncthreads();
            for (int j = tid; j < cn; j += 128) {
                int s = g_csr[s0 + c0 + j];
                ssrc[j] = s;
                float4 a = *(const float4*)&asrc[s * HH];
                float e0 = a.x + ad4.x; e0 = (e0 > 0.f) ? e0 : SLOPE * e0;
                float e1 = a.y + ad4.y; e1 = (e1 > 0.f) ? e1 : SLOPE * e1;
                float e2 = a.z + ad4.z; e2 = (e2 > 0.f) ? e2 : SLOPE * e2;
                float e3 = a.w + ad4.w; e3 = (e3 > 0.f) ? e3 : SLOPE * e3;
                sexp[j * HH + 0] = __expf(e0); sexp[j * HH + 1] = __expf(e1);
                sexp[j * HH + 2] = __expf(e2); sexp[j * HH + 3] = __expf(e3);
            }
            __syncthreads();
            for (int j = 0; j < cn; j++) {
                int s = ssrc[j];
                float e = sexp[j * HH + head];
                const __half2* p = (const __half2*)(h + (size_t)s * CH) + hoff;
                #pragma unroll
                for (int q = 0; q < VEC / 2; q++) {
                    float2 f = __half22float2(p[q]);
                    acc[q * 2]     += e * f.x;
                    acc[q * 2 + 1] += e * f.y;
                }
            }
        }
    }

    // elu + bias, write fp16
    float v0 = acc[0] * ih + bias[tid * VEC + 0];
    float v1 = acc[1] * ih + bias[tid * VEC + 1];
    v0 = (v0 > 0.f) ? v0 : expm1f(v0);
    v1 = (v1 > 0.f) ? v1 : expm1f(v1);
    __half2* op = (__half2*)(out + (size_t)d * CH + tid * VEC);
    op[0] = __floats2half2_rn(v0, v1);
    if (VEC == 4) {
        float v2 = acc[2] * ih + bias[tid * VEC + 2];
        float v3 = acc[3] * ih + bias[tid * VEC + 3];
        v2 = (v2 > 0.f) ? v2 : expm1f(v2);
        v3 = (v3 > 0.f) ? v3 : expm1f(v3);
        op[1] = __floats2half2_rn(v2, v3);
    }
}

// ---------------- launch ----------------------------------------------------
extern "C" void kernel_launch(void* const* d_in, const int* in_sizes, int n_in,
                              void* d_out, int out_size)
{
    const float* x   = (const float*)d_in[0];
    const int*   ei  = (const int*)  d_in[1];
    const float* W1  = (const float*)d_in[2];
    const float* as1 = (const float*)d_in[3];
    const float* ad1 = (const float*)d_in[4];
    const float* b1  = (const float*)d_in[5];
    const float* W2  = (const float*)d_in[6];
    const float* as2 = (const float*)d_in[7];
    const float* ad2 = (const float*)d_in[8];
    const float* b2  = (const float*)d_in[9];
    const float* Wf  = (const float*)d_in[10];
    const float* bf  = (const float*)d_in[11];
    float* out = (float*)d_out;

    __half *xh, *W1h, *W2h, *Wfh, *h1h, *h2h, *g1h, *g2h;
    float *pas, *pad;
    cudaGetSymbolAddress((void**)&xh,  g_xh);
    cudaGetSymbolAddress((void**)&W1h, g_W1h);
    cudaGetSymbolAddress((void**)&W2h, g_W2h);
    cudaGetSymbolAddress((void**)&Wfh, g_Wfh);
    cudaGetSymbolAddress((void**)&h1h, g_h1h);
    cudaGetSymbolAddress((void**)&h2h, g_h2h);
    cudaGetSymbolAddress((void**)&g1h, g_g1h);
    cudaGetSymbolAddress((void**)&g2h, g_g2h);
    cudaGetSymbolAddress((void**)&pas, g_asrc);
    cudaGetSymbolAddress((void**)&pad, g_adst);

    cudaFuncSetAttribute(gemm_f16_kernel<1, true>,
                         cudaFuncAttributeMaxDynamicSharedMemorySize, GEMM_SMEM);
    cudaFuncSetAttribute(gemm_f16_kernel<2, true>,
                         cudaFuncAttributeMaxDynamicSharedMemorySize, GEMM_SMEM);
    cudaFuncSetAttribute(gemm_f16_kernel<0, false>,
                         cudaFuncAttributeMaxDynamicSharedMemorySize, GEMM_SMEM);

    int grid_y = (NN + 255) / 256;   // 196

    // Launch order keeps GEMM1 as the 4th launch (ncu fixed-skip capture).
    zero_deg_kernel<<<(NN + 255) / 256, 256>>>();
    count_deg_kernel<<<(ETOT + 255) / 256, 256>>>(ei);
    convert_inputs_kernel<<<(NN * FIN / 4 + 255) / 256, 256>>>(x, W1, W2, Wf);

    // Layer 1 GEMM (+ fused attn coefs, fp16 h out)
    gemm_f16_kernel<1, true><<<dim3(CH1 / 128, grid_y), 256, GEMM_SMEM>>>(
        NN, CH1, FIN, xh, W1h, (float*)nullptr, h1h, CH1, CH1, (const float*)nullptr,
        as1, ad1, pas, pad);

    // CSR build
    scan1_kernel<<<NBLK, 256>>>();
    scan2_kernel<<<1, 256>>>();
    scan3_kernel<<<NBLK, 256>>>();
    scatter_edges_kernel<<<(ETOT + 255) / 256, 256>>>(ei);

    gat_agg_kernel<CH1><<<NN, 128>>>(h1h, pas, pad, b1, g1h);

    // Layer 2
    gemm_f16_kernel<2, true><<<dim3(CH2 / 128, grid_y), 256, GEMM_SMEM>>>(
        NN, CH2, CH1, g1h, W2h, (float*)nullptr, h2h, CH2, CH2, (const float*)nullptr,
        as2, ad2, pas, pad);
    gat_agg_kernel<CH2><<<NN, 128>>>(h2h, pas, pad, b2, g2h);

    // Final classifier: out[N,50] = g2 @ Wfpad + bf
    gemm_f16_kernel<0, false><<<dim3(1, grid_y), 256, GEMM_SMEM>>>(
        NN, 128, CH2, g2h, Wfh, out, (__half*)nullptr, NCLS, NCLS, bf,
        (const float*)nullptr, (const float*)nullptr,
        (float*)nullptr, (float*)nullptr);
}